// round 8
// baseline (speedup 1.0000x reference)
#include <cuda_runtime.h>
#include <math.h>

#define NB    1024
#define SIN   256
#define SPR   128
#define HIDN  512

// 1/sqrt(3) * log2(e): fold scores into exp2 domain
#define C_SCALE 0.83294064f
// log2(e): additive causal "mask" of +1.0 in exp2 domain
#define L2E 1.4426950408889634f
#define ABS2_MASK 0x7FFFFFFF7FFFFFFFULL

typedef unsigned long long u64;

struct Params {
    const float* X;           const float* T;
    const float* enc_in_w;    const float* enc_in_b;
    const float* enc_out_w;   const float* enc_out_b;
    const float* enc_ln1_w;   const float* enc_ln1_b;
    const float* enc_lin1_w;  const float* enc_lin1_b;
    const float* enc_lin2_w;  const float* enc_lin2_b;
    const float* enc_ln2_w;   const float* enc_ln2_b;
    const float* dec_a1_in_w; const float* dec_a1_in_b;
    const float* dec_a1_out_w;const float* dec_a1_out_b;
    const float* dec_ln1_w;   const float* dec_ln1_b;
    const float* dec_a2_in_w; const float* dec_a2_in_b;
    const float* dec_a2_out_w;const float* dec_a2_out_b;
    const float* dec_lin1_w;  const float* dec_lin1_b;
    const float* dec_lin2_w;  const float* dec_lin2_b;
    const float* dec_ln3_w;   const float* dec_ln3_b;
    float* out;
};

__device__ __forceinline__ float ex2f(float x) {
    float y; asm("ex2.approx.ftz.f32 %0, %1;" : "=f"(y) : "f"(x)); return y;
}
__device__ __forceinline__ float rcpf(float x) {
    float y; asm("rcp.approx.ftz.f32 %0, %1;" : "=f"(y) : "f"(x)); return y;
}

// ---- packed f32x2 ops (Blackwell) ----
__device__ __forceinline__ u64 fma2(u64 a, u64 b, u64 c) {
    u64 d; asm("fma.rn.f32x2 %0, %1, %2, %3;" : "=l"(d) : "l"(a), "l"(b), "l"(c)); return d;
}
__device__ __forceinline__ u64 mul2(u64 a, u64 b) {
    u64 d; asm("mul.rn.f32x2 %0, %1, %2;" : "=l"(d) : "l"(a), "l"(b)); return d;
}
__device__ __forceinline__ u64 add2(u64 a, u64 b) {
    u64 d; asm("add.rn.f32x2 %0, %1, %2;" : "=l"(d) : "l"(a), "l"(b)); return d;
}
__device__ __forceinline__ u64 pack2(float lo, float hi) {
    u64 d; asm("mov.b64 %0, {%1, %2};" : "=l"(d) : "f"(lo), "f"(hi)); return d;
}
__device__ __forceinline__ void unpack2(u64 d, float& a, float& b) {
    asm("mov.b64 {%0, %1}, %2;" : "=f"(a), "=f"(b) : "l"(d));
}
__device__ __forceinline__ float hadd2(u64 d) {
    float a, b; unpack2(d, a, b); return a + b;
}

// One packed attention step: 2 keys vs 1 query. l folded into packed add.
__device__ __forceinline__ void qstep(u64 q0p, u64 q1p, u64 q2p,
                                      u64 xp, u64 yp, u64 zp,
                                      u64& aX, u64& aY, u64& aZ, u64& aL) {
    u64 d = fma2(q2p, zp, fma2(q1p, yp, mul2(q0p, xp)));
    float s0, s1; unpack2(d, s0, s1);
    u64 pp = pack2(ex2f(s0), ex2f(s1));
    aX = fma2(pp, xp, aX);
    aY = fma2(pp, yp, aY);
    aZ = fma2(pp, zp, aZ);
    aL = add2(aL, pp);
}
// Masked variant: reference ADDS tril(ones) to scores -> +log2(e) in exp2 domain.
__device__ __forceinline__ void qstep_m(u64 q0p, u64 q1p, u64 q2p,
                                        u64 xp, u64 yp, u64 zp,
                                        int j, int row,
                                        u64& aX, u64& aY, u64& aZ, u64& aL) {
    u64 d = fma2(q2p, zp, fma2(q1p, yp, mul2(q0p, xp)));
    float s0, s1; unpack2(d, s0, s1);
    s0 += (j     <= row) ? L2E : 0.f;
    s1 += (j + 1 <= row) ? L2E : 0.f;
    u64 pp = pack2(ex2f(s0), ex2f(s1));
    aX = fma2(pp, xp, aX);
    aY = fma2(pp, yp, aY);
    aZ = fma2(pp, zp, aZ);
    aL = add2(aL, pp);
}
__device__ __forceinline__ void hsum4(u64 aX, u64 aY, u64 aZ, u64 aL,
                                      float& x, float& y, float& z, float& l) {
    x = hadd2(aX); y = hadd2(aY); z = hadd2(aZ); l = hadd2(aL);
}

// Fused two-value block reduction (2 barriers).
__device__ __forceinline__ void block_sum2(float& a, float& b, float* red) {
    #pragma unroll
    for (int o = 16; o; o >>= 1) {
        a += __shfl_xor_sync(0xffffffffu, a, o);
        b += __shfl_xor_sync(0xffffffffu, b, o);
    }
    int w = threadIdx.x >> 5;
    if ((threadIdx.x & 31) == 0) { red[w] = a; red[8 + w] = b; }
    __syncthreads();
    if (threadIdx.x < 16) {
        float x = red[threadIdx.x];
        x += __shfl_xor_sync(0x0000ffffu, x, 4);
        x += __shfl_xor_sync(0x0000ffffu, x, 2);
        x += __shfl_xor_sync(0x0000ffffu, x, 1);
        if ((threadIdx.x & 7) == 0) red[16 + (threadIdx.x >> 3)] = x;
    }
    __syncthreads();
    a = red[16]; b = red[17];
}

// LN over nrows*3 elems jointly; var = E[x^2]-mean^2 single pass.
__device__ __forceinline__ void layer_norm(const float* src, float* dst, int nrows,
                                           float inv_n, const float* w, const float* bb,
                                           float* red) {
    int t = threadIdx.x;
    float x0 = 0.f, x1 = 0.f, x2 = 0.f;
    if (t < nrows) { x0 = src[t*3]; x1 = src[t*3+1]; x2 = src[t*3+2]; }
    float s1 = x0 + x1 + x2;
    float s2 = fmaf(x0, x0, fmaf(x1, x1, x2 * x2));
    block_sum2(s1, s2, red);
    float mean = s1 * inv_n;
    float var  = fmaf(-mean, mean, s2 * inv_n);
    float rs = rsqrtf(var + 1e-5f);
    if (t < nrows) {
        dst[t*3+0] = (x0 - mean) * rs * w[t*3+0] + bb[t*3+0];
        dst[t*3+1] = (x1 - mean) * rs * w[t*3+1] + bb[t*3+1];
        dst[t*3+2] = (x2 - mean) * rs * w[t*3+2] + bb[t*3+2];
    }
    __syncthreads();
}

// LN writing into SoA arrays (for cross-attn keys).
__device__ __forceinline__ void layer_norm_soa(const float* src,
                                               float* dX, float* dY, float* dZ, int nrows,
                                               float inv_n, const float* w, const float* bb,
                                               float* red) {
    int t = threadIdx.x;
    float x0 = 0.f, x1 = 0.f, x2 = 0.f;
    if (t < nrows) { x0 = src[t*3]; x1 = src[t*3+1]; x2 = src[t*3+2]; }
    float s1 = x0 + x1 + x2;
    float s2 = fmaf(x0, x0, fmaf(x1, x1, x2 * x2));
    block_sum2(s1, s2, red);
    float mean = s1 * inv_n;
    float var  = fmaf(-mean, mean, s2 * inv_n);
    float rs = rsqrtf(var + 1e-5f);
    if (t < nrows) {
        dX[t] = (x0 - mean) * rs * w[t*3+0] + bb[t*3+0];
        dY[t] = (x1 - mean) * rs * w[t*3+1] + bb[t*3+1];
        dZ[t] = (x2 - mean) * rs * w[t*3+2] + bb[t*3+2];
    }
    __syncthreads();
}

// Final LN -> global.
__device__ __forceinline__ void layer_norm_out(const float* src, float* gout, int nrows,
                                               float inv_n, const float* w, const float* bb,
                                               float* red) {
    int t = threadIdx.x;
    float x0 = 0.f, x1 = 0.f, x2 = 0.f;
    if (t < nrows) { x0 = src[t*3]; x1 = src[t*3+1]; x2 = src[t*3+2]; }
    float s1 = x0 + x1 + x2;
    float s2 = fmaf(x0, x0, fmaf(x1, x1, x2 * x2));
    block_sum2(s1, s2, red);
    float mean = s1 * inv_n;
    float var  = fmaf(-mean, mean, s2 * inv_n);
    float rs = rsqrtf(var + 1e-5f);
    if (t < nrows) {
        gout[t*3+0] = (x0 - mean) * rs * w[t*3+0] + bb[t*3+0];
        gout[t*3+1] = (x1 - mean) * rs * w[t*3+1] + bb[t*3+1];
        gout[t*3+2] = (x2 - mean) * rs * w[t*3+2] + bb[t*3+2];
    }
}

__device__ __forceinline__ void proj3(const float* w, const float* bias,
                                      float x0, float x1, float x2,
                                      float& o0, float& o1, float& o2) {
    o0 = fmaf(w[0], x0, fmaf(w[1], x1, fmaf(w[2], x2, bias[0])));
    o1 = fmaf(w[3], x0, fmaf(w[4], x1, fmaf(w[5], x2, bias[1])));
    o2 = fmaf(w[6], x0, fmaf(w[7], x1, fmaf(w[8], x2, bias[2])));
}
__device__ __forceinline__ void proj3T(const float* w,
                                       float x0, float x1, float x2,
                                       float& o0, float& o1, float& o2) {
    o0 = fmaf(w[0], x0, fmaf(w[3], x1, w[6] * x2));
    o1 = fmaf(w[1], x0, fmaf(w[4], x1, w[7] * x2));
    o2 = fmaf(w[2], x0, fmaf(w[5], x1, w[8] * x2));
}
// q' = (Wk^T (Wq x + bq)) * C_SCALE; bk dropped (cancels in softmax)
__device__ __forceinline__ void make_q(const float* in_w, const float* in_b,
                                       float x0, float x1, float x2,
                                       float& q0, float& q1, float& q2) {
    float t0, t1, t2;
    proj3(in_w, in_b, x0, x1, x2, t0, t1, t2);
    proj3T(in_w + 9, t0, t1, t2, q0, q1, q2);
    q0 *= C_SCALE; q1 *= C_SCALE; q2 *= C_SCALE;
}

// SoA FFN weight staging: W1x|W1y|W1z|B1|W2x'|W2y'|W2z' (each 512 floats).
// W2 pre-scaled by 0.5 for the relu(t)*w2 == (t+|t|)*(0.5*w2) identity (bit-exact).
__device__ __forceinline__ void load_wff_soa(float* sW, const float* w1, const float* b1,
                                             const float* w2) {
    for (int h = threadIdx.x; h < HIDN; h += 256) {
        sW[h]          = w1[h*3+0];
        sW[512 + h]    = w1[h*3+1];
        sW[1024 + h]   = w1[h*3+2];
        sW[1536 + h]   = b1[h];
        sW[2048 + h]   = 0.5f * w2[h];
        sW[2560 + h]   = 0.5f * w2[HIDN + h];
        sW[3072 + h]   = 0.5f * w2[2*HIDN + h];
    }
    __syncthreads();
}

// Packed FFN: 2 rows x (2h per iter) over [i0, i0+niter). Accumulators packed over h-lanes.
__device__ __forceinline__ void ffn2_packed(const float* sW, int i0, int niter,
                                            u64 xA0, u64 xA1, u64 xA2,
                                            u64 xB0, u64 xB1, u64 xB2,
                                            float3& outA, float3& outB) {
    const u64* W1x = (const u64*)sW;
    const u64* W1y = (const u64*)(sW + 512);
    const u64* W1z = (const u64*)(sW + 1024);
    const u64* B1  = (const u64*)(sW + 1536);
    const u64* W2x = (const u64*)(sW + 2048);
    const u64* W2y = (const u64*)(sW + 2560);
    const u64* W2z = (const u64*)(sW + 3072);
    u64 aA0 = 0, aA1 = 0, aA2 = 0, aB0 = 0, aB1 = 0, aB2 = 0;
    #pragma unroll 2
    for (int i = i0; i < i0 + niter; ++i) {
        u64 w1x = W1x[i], w1y = W1y[i], w1z = W1z[i], b1p = B1[i];
        u64 tA = fma2(xA2, w1z, fma2(xA1, w1y, fma2(xA0, w1x, b1p)));
        u64 tB = fma2(xB2, w1z, fma2(xB1, w1y, fma2(xB0, w1x, b1p)));
        u64 sA = add2(tA, tA & ABS2_MASK);   // 2*relu(t)
        u64 sB = add2(tB, tB & ABS2_MASK);
        u64 w2x = W2x[i], w2y = W2y[i], w2z = W2z[i];
        aA0 = fma2(sA, w2x, aA0); aA1 = fma2(sA, w2y, aA1); aA2 = fma2(sA, w2z, aA2);
        aB0 = fma2(sB, w2x, aB0); aB1 = fma2(sB, w2y, aB1); aB2 = fma2(sB, w2z, aB2);
    }
    outA.x = hadd2(aA0); outA.y = hadd2(aA1); outA.z = hadd2(aA2);
    outB.x = hadd2(aB0); outB.y = hadd2(aB1); outB.z = hadd2(aB2);
}

// pos_enc row s: first 3 sin columns, invf[e] = 10000^(-2e/256)
__device__ __forceinline__ void pos3(int s, float& p0, float& p1, float& p2) {
    const float f1 = (float)0.93057204868496882;  // 10000^(-2/256)
    const float f2 = (float)0.86596432336006538;  // 10000^(-4/256)
    float a0 = (float)s;
    p0 = sinf(a0);
    p1 = sinf(a0 * f1);
    p2 = sinf(a0 * f2);
}

// One CTA = one batch. Grid caps occupancy at ~7 CTAs/SM.
__global__ void __launch_bounds__(256, 7)
fused_transformer_kernel(Params P) {
    // 16KB union s_U, time-multiplexed:
    //   attn: SoA keys (enc: sf[0..768), pT: sf[768..1152)) + partials s_U[320..576)
    //   ffn:  SoA weights sf[0..3584), then FFN row-partials (after a sync)
    __shared__ __align__(16) float4 s_U[1024];
    __shared__ float s_x2[SIN * 3];
    __shared__ float s_R[SIN * 3];
    __shared__ float s_red[18];

    float* const sf = (float*)s_U;
    float* const sX = sf;            // 256 floats (enc keys / enc_out keys)
    float* const sY = sf + 256;
    float* const sZ = sf + 512;
    float* const pX = sf + 768;      // 128 floats (pT keys)
    float* const pY = sf + 896;
    float* const pZ = sf + 1024;
    float4* const s_part = s_U + 320;  // attn partials

    const int b    = blockIdx.x;
    const int t    = threadIdx.x;
    const int r128 = t & 127, half2 = t >> 7;
    const float INV768 = 1.0f / 768.0f;
    const float INV384 = 1.0f / 384.0f;

    float pe0, pe1, pe2;
    pos3(t, pe0, pe1, pe2);

    // ================= ENCODER =================
    // E1: pX = X + pos_enc -> SoA keys
    {
        const float* xr = P.X + ((size_t)b * SIN + t) * 3;
        sX[t] = xr[0] + pe0;
        sY[t] = xr[1] + pe1;
        sZ[t] = xr[2] + pe2;
    }
    __syncthreads();

    // E2: self-attention. 1 query (row t) x all 256 keys, packed f32x2.
    {
        float x0 = sX[t], x1 = sY[t], x2v = sZ[t];
        float q0, q1, q2;
        make_q(P.enc_in_w, P.enc_in_b, x0, x1, x2v, q0, q1, q2);
        u64 q0p = pack2(q0, q0), q1p = pack2(q1, q1), q2p = pack2(q2, q2);
        u64 aX = 0, aY = 0, aZ = 0, aL = 0;
        const double2* X2 = (const double2*)sX;
        const double2* Y2 = (const double2*)sY;
        const double2* Z2 = (const double2*)sZ;
        #pragma unroll 4
        for (int i = 0; i < 64; ++i) {
            double2 dx = X2[i], dy = Y2[i], dz = Z2[i];
            qstep(q0p, q1p, q2p,
                  __double_as_longlong(dx.x), __double_as_longlong(dy.x), __double_as_longlong(dz.x),
                  aX, aY, aZ, aL);
            qstep(q0p, q1p, q2p,
                  __double_as_longlong(dx.y), __double_as_longlong(dy.y), __double_as_longlong(dz.y),
                  aX, aY, aZ, aL);
        }
        float ax, ay, az, l;
        hsum4(aX, aY, aZ, aL, ax, ay, az, l);
        float inv = rcpf(l);
        float v0, v1, v2;
        proj3(P.enc_in_w + 18, P.enc_in_b + 6, ax*inv, ay*inv, az*inv, v0, v1, v2);
        float r0, r1, r2;
        proj3(P.enc_out_w, P.enc_out_b, v0, v1, v2, r0, r1, r2);
        s_R[t*3+0] = r0 + x0;
        s_R[t*3+1] = r1 + x1;
        s_R[t*3+2] = r2 + x2v;
    }
    __syncthreads();
    layer_norm(s_R, s_x2, SIN, INV768, P.enc_ln1_w, P.enc_ln1_b, s_red);

    // E3: FFN. 2 rows {r128, r128+128} x 256 hidden (half2 split), packed over h-pairs.
    load_wff_soa(sf, P.enc_lin1_w, P.enc_lin1_b, P.enc_lin2_w);
    {
        int rowA = r128, rowB = r128 + 128;
        u64 xA0 = pack2(s_x2[rowA*3],   s_x2[rowA*3]);
        u64 xA1 = pack2(s_x2[rowA*3+1], s_x2[rowA*3+1]);
        u64 xA2 = pack2(s_x2[rowA*3+2], s_x2[rowA*3+2]);
        u64 xB0 = pack2(s_x2[rowB*3],   s_x2[rowB*3]);
        u64 xB1 = pack2(s_x2[rowB*3+1], s_x2[rowB*3+1]);
        u64 xB2 = pack2(s_x2[rowB*3+2], s_x2[rowB*3+2]);
        float3 oA, oB;
        ffn2_packed(sf, half2 * 128, 128, xA0, xA1, xA2, xB0, xB1, xB2, oA, oB);
        __syncthreads();   // weights fully consumed; s_U becomes partial buffer
        s_U[half2*256 + rowA] = make_float4(oA.x, oA.y, oA.z, 0.f);
        s_U[half2*256 + rowB] = make_float4(oB.x, oB.y, oB.z, 0.f);
    }
    __syncthreads();
    {
        float4 p0 = s_U[t], p1 = s_U[256 + t];
        float eb0 = P.enc_lin2_b[0], eb1 = P.enc_lin2_b[1], eb2 = P.enc_lin2_b[2];
        s_R[t*3+0] = p0.x + p1.x + eb0 + s_x2[t*3+0];
        s_R[t*3+1] = p0.y + p1.y + eb1 + s_x2[t*3+1];
        s_R[t*3+2] = p0.z + p1.z + eb2 + s_x2[t*3+2];
    }
    __syncthreads();
    // LN2 -> enc_out straight into SoA key arrays (for cross-attn)
    layer_norm_soa(s_R, sX, sY, sZ, SIN, INV768, P.enc_ln2_w, P.enc_ln2_b, s_red);

    // ================= DECODER =================
    // D1: pT -> SoA (pX/pY/pZ)
    if (t < SPR) {
        const float* tr = P.T + ((size_t)b * SPR + t) * 3;
        pX[t] = tr[0] + pe0;
        pY[t] = tr[1] + pe1;
        pZ[t] = tr[2] + pe2;
    }
    __syncthreads();

    // D2: dec self-attn. query r128, keys [half2*64, +64), causal +1 mask.
    {
        int row = r128;
        float x0 = pX[row], x1 = pY[row], x2v = pZ[row];
        float q0, q1, q2;
        make_q(P.dec_a1_in_w, P.dec_a1_in_b, x0, x1, x2v, q0, q1, q2);
        u64 q0p = pack2(q0, q0), q1p = pack2(q1, q1), q2p = pack2(q2, q2);
        u64 aX = 0, aY = 0, aZ = 0, aL = 0;
        const double2* X2 = (const double2*)pX;
        const double2* Y2 = (const double2*)pY;
        const double2* Z2 = (const double2*)pZ;
        int i0 = half2 * 16;
        #pragma unroll 4
        for (int i = i0; i < i0 + 16; ++i) {
            int j = i * 4;
            double2 dx = X2[i], dy = Y2[i], dz = Z2[i];
            qstep_m(q0p, q1p, q2p,
                    __double_as_longlong(dx.x), __double_as_longlong(dy.x), __double_as_longlong(dz.x),
                    j, row, aX, aY, aZ, aL);
            qstep_m(q0p, q1p, q2p,
                    __double_as_longlong(dx.y), __double_as_longlong(dy.y), __double_as_longlong(dz.y),
                    j + 2, row, aX, aY, aZ, aL);
        }
        float ax, ay, az, l;
        hsum4(aX, aY, aZ, aL, ax, ay, az, l);
        s_part[row*2 + half2] = make_float4(l, ax, ay, az);
    }
    __syncthreads();
    if (t < SPR) {
        float4 pa = s_part[t*2], pb = s_part[t*2+1];
        float inv = rcpf(pa.x + pb.x);
        float v0, v1, v2;
        proj3(P.dec_a1_in_w + 18, P.dec_a1_in_b + 6,
              (pa.y+pb.y)*inv, (pa.z+pb.z)*inv, (pa.w+pb.w)*inv, v0, v1, v2);
        float r0, r1, r2;
        proj3(P.dec_a1_out_w, P.dec_a1_out_b, v0, v1, v2, r0, r1, r2);
        s_R[t*3+0] = r0 + pX[t];
        s_R[t*3+1] = r1 + pY[t];
        s_R[t*3+2] = r2 + pZ[t];
    }
    __syncthreads();
    layer_norm(s_R, s_x2, SPR, INV384, P.dec_ln1_w, P.dec_ln1_b, s_red);

    // D4: cross-attn. query r128 (x2), keys = enc_out SoA [half2*128, +128).
    {
        int row = r128;
        float q0, q1, q2;
        make_q(P.dec_a2_in_w, P.dec_a2_in_b,
               s_x2[row*3], s_x2[row*3+1], s_x2[row*3+2], q0, q1, q2);
        u64 q0p = pack2(q0, q0), q1p = pack2(q1, q1), q2p = pack2(q2, q2);
        u64 aX = 0, aY = 0, aZ = 0, aL = 0;
        const double2* X2 = (const double2*)sX;
        const double2* Y2 = (const double2*)sY;
        const double2* Z2 = (const double2*)sZ;
        int i0 = half2 * 32;
        #pragma unroll 4
        for (int i = i0; i < i0 + 32; ++i) {
            double2 dx = X2[i], dy = Y2[i], dz = Z2[i];
            qstep(q0p, q1p, q2p,
                  __double_as_longlong(dx.x), __double_as_longlong(dy.x), __double_as_longlong(dz.x),
                  aX, aY, aZ, aL);
            qstep(q0p, q1p, q2p,
                  __double_as_longlong(dx.y), __double_as_longlong(dy.y), __double_as_longlong(dz.y),
                  aX, aY, aZ, aL);
        }
        float ax, ay, az, l;
        hsum4(aX, aY, aZ, aL, ax, ay, az, l);
        s_part[row*2 + half2] = make_float4(l, ax, ay, az);
    }
    __syncthreads();
    if (t < SPR) {
        float4 pa = s_part[t*2], pb = s_part[t*2+1];
        float inv = rcpf(pa.x + pb.x);
        float v0, v1, v2;
        proj3(P.dec_a2_in_w + 18, P.dec_a2_in_b + 6,
              (pa.y+pb.y)*inv, (pa.z+pb.z)*inv, (pa.w+pb.w)*inv, v0, v1, v2);
        float r0, r1, r2;
        proj3(P.dec_a2_out_w, P.dec_a2_out_b, v0, v1, v2, r0, r1, r2);
        s_R[t*3+0] = r0 + s_x2[t*3+0];
        s_R[t*3+1] = r1 + s_x2[t*3+1];
        s_R[t*3+2] = r2 + s_x2[t*3+2];
    }
    __syncthreads();
    layer_norm(s_R, s_x2, SPR, INV384, P.dec_ln1_w, P.dec_ln1_b, s_red);  // x3

    // D5: dec FFN. 2 rows {r64, r64+64} x 128 hidden (quarter q4), packed over h-pairs.
    load_wff_soa(sf, P.dec_lin1_w, P.dec_lin1_b, P.dec_lin2_w);
    {
        const int r = t & 63, q4 = t >> 6;
        int rowA = r, rowB = r + 64;
        u64 xA0 = pack2(s_x2[rowA*3],   s_x2[rowA*3]);
        u64 xA1 = pack2(s_x2[rowA*3+1], s_x2[rowA*3+1]);
        u64 xA2 = pack2(s_x2[rowA*3+2], s_x2[rowA*3+2]);
        u64 xB0 = pack2(s_x2[rowB*3],   s_x2[rowB*3]);
        u64 xB1 = pack2(s_x2[rowB*3+1], s_x2[rowB*3+1]);
        u64 xB2 = pack2(s_x2[rowB*3+2], s_x2[rowB*3+2]);
        float3 oA, oB;
        ffn2_packed(sf, q4 * 64, 64, xA0, xA1, xA2, xB0, xB1, xB2, oA, oB);
        __syncthreads();   // weights consumed; s_U becomes partial buffer
        s_U[q4*128 + rowA] = make_float4(oA.x, oA.y, oA.z, 0.f);
        s_U[q4*128 + rowB] = make_float4(oB.x, oB.y, oB.z, 0.f);
    }
    __syncthreads();
    if (t < SPR) {
        float4 p0 = s_U[t], p1 = s_U[128+t], p2 = s_U[256+t], p3 = s_U[384+t];
        s_R[t*3+0] = p0.x+p1.x+p2.x+p3.x + P.dec_lin2_b[0] + s_x2[t*3+0];
        s_R[t*3+1] = p0.y+p1.y+p2.y+p3.y + P.dec_lin2_b[1] + s_x2[t*3+1];
        s_R[t*3+2] = p0.z+p1.z+p2.z+p3.z + P.dec_lin2_b[2] + s_x2[t*3+2];
    }
    __syncthreads();
    layer_norm_out(s_R, P.out + (size_t)b * SPR * 3, SPR, INV384,
                   P.dec_ln3_w, P.dec_ln3_b, s_red);
}

extern "C" void kernel_launch(void* const* d_in, const int* in_sizes, int n_in,
                              void* d_out, int out_size) {
    (void)in_sizes; (void)n_in; (void)out_size;
    Params P;
    P.X            = (const float*)d_in[0];
    P.T            = (const float*)d_in[1];
    P.enc_in_w     = (const float*)d_in[2];
    P.enc_in_b     = (const float*)d_in[3];
    P.enc_out_w    = (const float*)d_in[4];
    P.enc_out_b    = (const float*)d_in[5];
    P.enc_ln1_w    = (const float*)d_in[6];
    P.enc_ln1_b    = (const float*)d_in[7];
    P.enc_lin1_w   = (const float*)d_in[8];
    P.enc_lin1_b   = (const float*)d_in[9];
    P.enc_lin2_w   = (const float*)d_in[10];
    P.enc_lin2_b   = (const float*)d_in[11];
    P.enc_ln2_w    = (const float*)d_in[12];
    P.enc_ln2_b    = (const float*)d_in[13];
    P.dec_a1_in_w  = (const float*)d_in[14];
    P.dec_a1_in_b  = (const float*)d_in[15];
    P.dec_a1_out_w = (const float*)d_in[16];
    P.dec_a1_out_b = (const float*)d_in[17];
    P.dec_ln1_w    = (const float*)d_in[18];
    P.dec_ln1_b    = (const float*)d_in[19];
    P.dec_a2_in_w  = (const float*)d_in[20];
    P.dec_a2_in_b  = (const float*)d_in[21];
    P.dec_a2_out_w = (const float*)d_in[22];
    P.dec_a2_out_b = (const float*)d_in[23];
    P.dec_lin1_w   = (const float*)d_in[24];
    P.dec_lin1_b   = (const float*)d_in[25];
    P.dec_lin2_w   = (const float*)d_in[26];
    P.dec_lin2_b   = (const float*)d_in[27];
    P.dec_ln3_w    = (const float*)d_in[28];
    P.dec_ln3_b    = (const float*)d_in[29];
    P.out          = (float*)d_out;

    fused_transformer_kernel<<<NB, 256>>>(P);
}

// round 9
// speedup vs baseline: 1.7862x; 1.7862x over previous
#include <cuda_runtime.h>
#include <math.h>

#define NB    1024
#define SIN   256
#define SPR   128
#define HIDN  512

// 1/sqrt(3) * log2(e): fold scores into exp2 domain
#define C_SCALE 0.83294064f
// log2(e): additive causal "mask" of +1.0 in exp2 domain
#define L2E 1.4426950408889634f
#define ABS2_MASK 0x7FFFFFFF7FFFFFFFULL

typedef unsigned long long u64;

struct Params {
    const float* X;           const float* T;
    const float* enc_in_w;    const float* enc_in_b;
    const float* enc_out_w;   const float* enc_out_b;
    const float* enc_ln1_w;   const float* enc_ln1_b;
    const float* enc_lin1_w;  const float* enc_lin1_b;
    const float* enc_lin2_w;  const float* enc_lin2_b;
    const float* enc_ln2_w;   const float* enc_ln2_b;
    const float* dec_a1_in_w; const float* dec_a1_in_b;
    const float* dec_a1_out_w;const float* dec_a1_out_b;
    const float* dec_ln1_w;   const float* dec_ln1_b;
    const float* dec_a2_in_w; const float* dec_a2_in_b;
    const float* dec_a2_out_w;const float* dec_a2_out_b;
    const float* dec_lin1_w;  const float* dec_lin1_b;
    const float* dec_lin2_w;  const float* dec_lin2_b;
    const float* dec_ln3_w;   const float* dec_ln3_b;
    float* out;
};

__device__ __forceinline__ float ex2f(float x) {
    float y; asm("ex2.approx.ftz.f32 %0, %1;" : "=f"(y) : "f"(x)); return y;
}
__device__ __forceinline__ float rcpf(float x) {
    float y; asm("rcp.approx.ftz.f32 %0, %1;" : "=f"(y) : "f"(x)); return y;
}

// ---- packed f32x2 ops (Blackwell) ----
__device__ __forceinline__ u64 fma2(u64 a, u64 b, u64 c) {
    u64 d; asm("fma.rn.f32x2 %0, %1, %2, %3;" : "=l"(d) : "l"(a), "l"(b), "l"(c)); return d;
}
__device__ __forceinline__ u64 mul2(u64 a, u64 b) {
    u64 d; asm("mul.rn.f32x2 %0, %1, %2;" : "=l"(d) : "l"(a), "l"(b)); return d;
}
__device__ __forceinline__ u64 add2(u64 a, u64 b) {
    u64 d; asm("add.rn.f32x2 %0, %1, %2;" : "=l"(d) : "l"(a), "l"(b)); return d;
}
__device__ __forceinline__ u64 pack2(float lo, float hi) {
    u64 d; asm("mov.b64 %0, {%1, %2};" : "=l"(d) : "f"(lo), "f"(hi)); return d;
}
__device__ __forceinline__ void unpack2(u64 d, float& a, float& b) {
    asm("mov.b64 {%0, %1}, %2;" : "=f"(a), "=f"(b) : "l"(d));
}
__device__ __forceinline__ float hadd2(u64 d) {
    float a, b; unpack2(d, a, b); return a + b;
}

// One packed attention step: 2 keys vs 1 query. l folded into packed add.
__device__ __forceinline__ void qstep(u64 q0p, u64 q1p, u64 q2p,
                                      u64 xp, u64 yp, u64 zp,
                                      u64& aX, u64& aY, u64& aZ, u64& aL) {
    u64 d = fma2(q2p, zp, fma2(q1p, yp, mul2(q0p, xp)));
    float s0, s1; unpack2(d, s0, s1);
    u64 pp = pack2(ex2f(s0), ex2f(s1));
    aX = fma2(pp, xp, aX);
    aY = fma2(pp, yp, aY);
    aZ = fma2(pp, zp, aZ);
    aL = add2(aL, pp);
}
// Masked variant: reference ADDS tril(ones) to scores -> +log2(e) in exp2 domain.
__device__ __forceinline__ void qstep_m(u64 q0p, u64 q1p, u64 q2p,
                                        u64 xp, u64 yp, u64 zp,
                                        int j, int row,
                                        u64& aX, u64& aY, u64& aZ, u64& aL) {
    u64 d = fma2(q2p, zp, fma2(q1p, yp, mul2(q0p, xp)));
    float s0, s1; unpack2(d, s0, s1);
    s0 += (j     <= row) ? L2E : 0.f;
    s1 += (j + 1 <= row) ? L2E : 0.f;
    u64 pp = pack2(ex2f(s0), ex2f(s1));
    aX = fma2(pp, xp, aX);
    aY = fma2(pp, yp, aY);
    aZ = fma2(pp, zp, aZ);
    aL = add2(aL, pp);
}
__device__ __forceinline__ void hsum4(u64 aX, u64 aY, u64 aZ, u64 aL,
                                      float& x, float& y, float& z, float& l) {
    x = hadd2(aX); y = hadd2(aY); z = hadd2(aZ); l = hadd2(aL);
}

// Fused two-value block reduction (2 barriers).
__device__ __forceinline__ void block_sum2(float& a, float& b, float* red) {
    #pragma unroll
    for (int o = 16; o; o >>= 1) {
        a += __shfl_xor_sync(0xffffffffu, a, o);
        b += __shfl_xor_sync(0xffffffffu, b, o);
    }
    int w = threadIdx.x >> 5;
    if ((threadIdx.x & 31) == 0) { red[w] = a; red[8 + w] = b; }
    __syncthreads();
    if (threadIdx.x < 16) {
        float x = red[threadIdx.x];
        x += __shfl_xor_sync(0x0000ffffu, x, 4);
        x += __shfl_xor_sync(0x0000ffffu, x, 2);
        x += __shfl_xor_sync(0x0000ffffu, x, 1);
        if ((threadIdx.x & 7) == 0) red[16 + (threadIdx.x >> 3)] = x;
    }
    __syncthreads();
    a = red[16]; b = red[17];
}

// LN over nrows*3 elems jointly; var = E[x^2]-mean^2 single pass.
__device__ __forceinline__ void layer_norm(const float* src, float* dst, int nrows,
                                           float inv_n, const float* w, const float* bb,
                                           float* red) {
    int t = threadIdx.x;
    float x0 = 0.f, x1 = 0.f, x2 = 0.f;
    if (t < nrows) { x0 = src[t*3]; x1 = src[t*3+1]; x2 = src[t*3+2]; }
    float s1 = x0 + x1 + x2;
    float s2 = fmaf(x0, x0, fmaf(x1, x1, x2 * x2));
    block_sum2(s1, s2, red);
    float mean = s1 * inv_n;
    float var  = fmaf(-mean, mean, s2 * inv_n);
    float rs = rsqrtf(var + 1e-5f);
    if (t < nrows) {
        dst[t*3+0] = (x0 - mean) * rs * w[t*3+0] + bb[t*3+0];
        dst[t*3+1] = (x1 - mean) * rs * w[t*3+1] + bb[t*3+1];
        dst[t*3+2] = (x2 - mean) * rs * w[t*3+2] + bb[t*3+2];
    }
    __syncthreads();
}

// LN writing into SoA arrays (for cross-attn keys).
__device__ __forceinline__ void layer_norm_soa(const float* src,
                                               float* dX, float* dY, float* dZ, int nrows,
                                               float inv_n, const float* w, const float* bb,
                                               float* red) {
    int t = threadIdx.x;
    float x0 = 0.f, x1 = 0.f, x2 = 0.f;
    if (t < nrows) { x0 = src[t*3]; x1 = src[t*3+1]; x2 = src[t*3+2]; }
    float s1 = x0 + x1 + x2;
    float s2 = fmaf(x0, x0, fmaf(x1, x1, x2 * x2));
    block_sum2(s1, s2, red);
    float mean = s1 * inv_n;
    float var  = fmaf(-mean, mean, s2 * inv_n);
    float rs = rsqrtf(var + 1e-5f);
    if (t < nrows) {
        dX[t] = (x0 - mean) * rs * w[t*3+0] + bb[t*3+0];
        dY[t] = (x1 - mean) * rs * w[t*3+1] + bb[t*3+1];
        dZ[t] = (x2 - mean) * rs * w[t*3+2] + bb[t*3+2];
    }
    __syncthreads();
}

// Final LN -> global.
__device__ __forceinline__ void layer_norm_out(const float* src, float* gout, int nrows,
                                               float inv_n, const float* w, const float* bb,
                                               float* red) {
    int t = threadIdx.x;
    float x0 = 0.f, x1 = 0.f, x2 = 0.f;
    if (t < nrows) { x0 = src[t*3]; x1 = src[t*3+1]; x2 = src[t*3+2]; }
    float s1 = x0 + x1 + x2;
    float s2 = fmaf(x0, x0, fmaf(x1, x1, x2 * x2));
    block_sum2(s1, s2, red);
    float mean = s1 * inv_n;
    float var  = fmaf(-mean, mean, s2 * inv_n);
    float rs = rsqrtf(var + 1e-5f);
    if (t < nrows) {
        gout[t*3+0] = (x0 - mean) * rs * w[t*3+0] + bb[t*3+0];
        gout[t*3+1] = (x1 - mean) * rs * w[t*3+1] + bb[t*3+1];
        gout[t*3+2] = (x2 - mean) * rs * w[t*3+2] + bb[t*3+2];
    }
}

__device__ __forceinline__ void proj3(const float* w, const float* bias,
                                      float x0, float x1, float x2,
                                      float& o0, float& o1, float& o2) {
    o0 = fmaf(w[0], x0, fmaf(w[1], x1, fmaf(w[2], x2, bias[0])));
    o1 = fmaf(w[3], x0, fmaf(w[4], x1, fmaf(w[5], x2, bias[1])));
    o2 = fmaf(w[6], x0, fmaf(w[7], x1, fmaf(w[8], x2, bias[2])));
}
__device__ __forceinline__ void proj3T(const float* w,
                                       float x0, float x1, float x2,
                                       float& o0, float& o1, float& o2) {
    o0 = fmaf(w[0], x0, fmaf(w[3], x1, w[6] * x2));
    o1 = fmaf(w[1], x0, fmaf(w[4], x1, w[7] * x2));
    o2 = fmaf(w[2], x0, fmaf(w[5], x1, w[8] * x2));
}
// q' = (Wk^T (Wq x + bq)) * C_SCALE; bk dropped (cancels in softmax)
__device__ __forceinline__ void make_q(const float* in_w, const float* in_b,
                                       float x0, float x1, float x2,
                                       float& q0, float& q1, float& q2) {
    float t0, t1, t2;
    proj3(in_w, in_b, x0, x1, x2, t0, t1, t2);
    proj3T(in_w + 9, t0, t1, t2, q0, q1, q2);
    q0 *= C_SCALE; q1 *= C_SCALE; q2 *= C_SCALE;
}

// Paired-h AoS FFN staging: per h-pair i (h0=2i, h1=2i+1), 4 float4:
//   [w1x0,w1x1,w1y0,w1y1] [w1z0,w1z1,b0,b1] [w2x0',w2x1',w2y0',w2y1'] [w2z0',w2z1',0,0]
// W2 pre-scaled by 0.5 for relu(t)*w2 == (t+|t|)*(0.5*w2) (bit-exact).
__device__ __forceinline__ void load_wff_pack(float4* s4, const float* w1, const float* b1,
                                              const float* w2) {
    int i = threadIdx.x;            // 256 threads, one h-pair each
    int h0 = 2*i, h1 = 2*i + 1;
    s4[4*i+0] = make_float4(w1[h0*3],   w1[h1*3],   w1[h0*3+1], w1[h1*3+1]);
    s4[4*i+1] = make_float4(w1[h0*3+2], w1[h1*3+2], b1[h0],     b1[h1]);
    s4[4*i+2] = make_float4(0.5f*w2[h0],      0.5f*w2[h1],
                            0.5f*w2[512+h0],  0.5f*w2[512+h1]);
    s4[4*i+3] = make_float4(0.5f*w2[1024+h0], 0.5f*w2[1024+h1], 0.f, 0.f);
    __syncthreads();
}

// Packed FFN: 2 rows x (2h per iter), h-pair range [i0, i0+niter).
__device__ __forceinline__ void ffn_pack(const ulonglong2* g, int i0, int niter,
                                         u64 xA0, u64 xA1, u64 xA2,
                                         u64 xB0, u64 xB1, u64 xB2,
                                         float3& oA, float3& oB) {
    u64 aA0 = 0, aA1 = 0, aA2 = 0, aB0 = 0, aB1 = 0, aB2 = 0;
    const ulonglong2* p = g + 4*i0;
    #pragma unroll 2
    for (int i = 0; i < niter; ++i, p += 4) {
        ulonglong2 g0 = p[0], g1 = p[1];
        u64 tA = fma2(xA2, g1.x, fma2(xA1, g0.y, fma2(xA0, g0.x, g1.y)));
        u64 tB = fma2(xB2, g1.x, fma2(xB1, g0.y, fma2(xB0, g0.x, g1.y)));
        u64 sA = add2(tA, tA & ABS2_MASK);   // 2*relu(t)
        u64 sB = add2(tB, tB & ABS2_MASK);
        ulonglong2 g2 = p[2], g3 = p[3];
        aA0 = fma2(sA, g2.x, aA0); aA1 = fma2(sA, g2.y, aA1); aA2 = fma2(sA, g3.x, aA2);
        aB0 = fma2(sB, g2.x, aB0); aB1 = fma2(sB, g2.y, aB1); aB2 = fma2(sB, g3.x, aB2);
    }
    oA = make_float3(hadd2(aA0), hadd2(aA1), hadd2(aA2));
    oB = make_float3(hadd2(aB0), hadd2(aB1), hadd2(aB2));
}

// pos_enc row s: first 3 sin columns, invf[e] = 10000^(-2e/256)
__device__ __forceinline__ void pos3(int s, float& p0, float& p1, float& p2) {
    const float f1 = (float)0.93057204868496882;  // 10000^(-2/256)
    const float f2 = (float)0.86596432336006538;  // 10000^(-4/256)
    float a0 = (float)s;
    p0 = sinf(a0);
    p1 = sinf(a0 * f1);
    p2 = sinf(a0 * f2);
}

// One CTA = one batch. Grid caps occupancy at ~7 CTAs/SM.
__global__ void __launch_bounds__(256, 7)
fused_transformer_kernel(Params P) {
    // 16KB union s_U, time-multiplexed:
    //   attn: SoA keys (enc: sf[0..768), pT: sf[768..1152)) + partials s_U[320..576)
    //   ffn:  paired-h AoS weights (4 float4 per h-pair) over all 16KB
    __shared__ __align__(16) float4 s_U[1024];
    __shared__ float s_x2[SIN * 3];
    __shared__ float s_R[SIN * 3];
    __shared__ float s_E[SIN * 3];
    __shared__ float s_red[18];

    float* const sf = (float*)s_U;
    float* const sX = sf;            // 256 floats (enc keys / enc_out keys)
    float* const sY = sf + 256;
    float* const sZ = sf + 512;
    float* const pX = sf + 768;      // 128 floats (pT keys)
    float* const pY = sf + 896;
    float* const pZ = sf + 1024;
    float4* const s_part = s_U + 320;  // attn partials

    const int b    = blockIdx.x;
    const int t    = threadIdx.x;
    const int r128 = t & 127, half2 = t >> 7;
    const float INV768 = 1.0f / 768.0f;
    const float INV384 = 1.0f / 384.0f;

    float pe0, pe1, pe2;
    pos3(t, pe0, pe1, pe2);

    // ================= ENCODER =================
    // E1: pX = X + pos_enc -> SoA keys
    {
        const float* xr = P.X + ((size_t)b * SIN + t) * 3;
        sX[t] = xr[0] + pe0;
        sY[t] = xr[1] + pe1;
        sZ[t] = xr[2] + pe2;
    }
    __syncthreads();

    // E2: self-attention. 1 query (row t) x all 256 keys, packed f32x2.
    {
        float x0 = sX[t], x1 = sY[t], x2v = sZ[t];
        float q0, q1, q2;
        make_q(P.enc_in_w, P.enc_in_b, x0, x1, x2v, q0, q1, q2);
        u64 q0p = pack2(q0, q0), q1p = pack2(q1, q1), q2p = pack2(q2, q2);
        u64 aX = 0, aY = 0, aZ = 0, aL = 0;
        const double2* X2 = (const double2*)sX;
        const double2* Y2 = (const double2*)sY;
        const double2* Z2 = (const double2*)sZ;
        #pragma unroll 4
        for (int i = 0; i < 64; ++i) {
            double2 dx = X2[i], dy = Y2[i], dz = Z2[i];
            qstep(q0p, q1p, q2p,
                  __double_as_longlong(dx.x), __double_as_longlong(dy.x), __double_as_longlong(dz.x),
                  aX, aY, aZ, aL);
            qstep(q0p, q1p, q2p,
                  __double_as_longlong(dx.y), __double_as_longlong(dy.y), __double_as_longlong(dz.y),
                  aX, aY, aZ, aL);
        }
        float ax, ay, az, l;
        hsum4(aX, aY, aZ, aL, ax, ay, az, l);
        float inv = rcpf(l);
        float v0, v1, v2;
        proj3(P.enc_in_w + 18, P.enc_in_b + 6, ax*inv, ay*inv, az*inv, v0, v1, v2);
        float r0, r1, r2;
        proj3(P.enc_out_w, P.enc_out_b, v0, v1, v2, r0, r1, r2);
        s_R[t*3+0] = r0 + x0;
        s_R[t*3+1] = r1 + x1;
        s_R[t*3+2] = r2 + x2v;
    }
    __syncthreads();
    layer_norm(s_R, s_x2, SIN, INV768, P.enc_ln1_w, P.enc_ln1_b, s_red);

    // E3: FFN. 2 rows {r128, r128+128} x 128 h-pairs (half2 split), packed math.
    load_wff_pack(s_U, P.enc_lin1_w, P.enc_lin1_b, P.enc_lin2_w);
    {
        int rowA = r128, rowB = r128 + 128;
        u64 xA0 = pack2(s_x2[rowA*3],   s_x2[rowA*3]);
        u64 xA1 = pack2(s_x2[rowA*3+1], s_x2[rowA*3+1]);
        u64 xA2 = pack2(s_x2[rowA*3+2], s_x2[rowA*3+2]);
        u64 xB0 = pack2(s_x2[rowB*3],   s_x2[rowB*3]);
        u64 xB1 = pack2(s_x2[rowB*3+1], s_x2[rowB*3+1]);
        u64 xB2 = pack2(s_x2[rowB*3+2], s_x2[rowB*3+2]);
        float3 oA, oB;
        ffn_pack((const ulonglong2*)s_U, half2 * 128, 128,
                 xA0, xA1, xA2, xB0, xB1, xB2, oA, oB);
        float* dst = half2 ? s_R : s_E;
        dst[rowA*3+0]=oA.x; dst[rowA*3+1]=oA.y; dst[rowA*3+2]=oA.z;
        dst[rowB*3+0]=oB.x; dst[rowB*3+1]=oB.y; dst[rowB*3+2]=oB.z;
    }
    __syncthreads();
    {
        float eb0 = P.enc_lin2_b[0], eb1 = P.enc_lin2_b[1], eb2 = P.enc_lin2_b[2];
        s_R[t*3+0] = s_E[t*3+0] + s_R[t*3+0] + eb0 + s_x2[t*3+0];
        s_R[t*3+1] = s_E[t*3+1] + s_R[t*3+1] + eb1 + s_x2[t*3+1];
        s_R[t*3+2] = s_E[t*3+2] + s_R[t*3+2] + eb2 + s_x2[t*3+2];
    }
    __syncthreads();
    // LN2 -> enc_out straight into SoA key arrays (for cross-attn)
    layer_norm_soa(s_R, sX, sY, sZ, SIN, INV768, P.enc_ln2_w, P.enc_ln2_b, s_red);

    // ================= DECODER =================
    // D1: pT -> SoA (pX/pY/pZ)
    if (t < SPR) {
        const float* tr = P.T + ((size_t)b * SPR + t) * 3;
        pX[t] = tr[0] + pe0;
        pY[t] = tr[1] + pe1;
        pZ[t] = tr[2] + pe2;
    }
    __syncthreads();

    // D2: dec self-attn. query r128, keys [half2*64, +64), causal +1 mask.
    {
        int row = r128;
        float x0 = pX[row], x1 = pY[row], x2v = pZ[row];
        float q0, q1, q2;
        make_q(P.dec_a1_in_w, P.dec_a1_in_b, x0, x1, x2v, q0, q1, q2);
        u64 q0p = pack2(q0, q0), q1p = pack2(q1, q1), q2p = pack2(q2, q2);
        u64 aX = 0, aY = 0, aZ = 0, aL = 0;
        const double2* X2 = (const double2*)pX;
        const double2* Y2 = (const double2*)pY;
        const double2* Z2 = (const double2*)pZ;
        int i0 = half2 * 16;
        #pragma unroll 4
        for (int i = i0; i < i0 + 16; ++i) {
            int j = i * 4;
            double2 dx = X2[i], dy = Y2[i], dz = Z2[i];
            qstep_m(q0p, q1p, q2p,
                    __double_as_longlong(dx.x), __double_as_longlong(dy.x), __double_as_longlong(dz.x),
                    j, row, aX, aY, aZ, aL);
            qstep_m(q0p, q1p, q2p,
                    __double_as_longlong(dx.y), __double_as_longlong(dy.y), __double_as_longlong(dz.y),
                    j + 2, row, aX, aY, aZ, aL);
        }
        float ax, ay, az, l;
        hsum4(aX, aY, aZ, aL, ax, ay, az, l);
        s_part[row*2 + half2] = make_float4(l, ax, ay, az);
    }
    __syncthreads();
    if (t < SPR) {
        float4 pa = s_part[t*2], pb = s_part[t*2+1];
        float inv = rcpf(pa.x + pb.x);
        float v0, v1, v2;
        proj3(P.dec_a1_in_w + 18, P.dec_a1_in_b + 6,
              (pa.y+pb.y)*inv, (pa.z+pb.z)*inv, (pa.w+pb.w)*inv, v0, v1, v2);
        float r0, r1, r2;
        proj3(P.dec_a1_out_w, P.dec_a1_out_b, v0, v1, v2, r0, r1, r2);
        s_R[t*3+0] = r0 + pX[t];
        s_R[t*3+1] = r1 + pY[t];
        s_R[t*3+2] = r2 + pZ[t];
    }
    __syncthreads();
    layer_norm(s_R, s_x2, SPR, INV384, P.dec_ln1_w, P.dec_ln1_b, s_red);

    // D4: cross-attn. query r128 (x2), keys = enc_out SoA [half2*128, +128).
    {
        int row = r128;
        float q0, q1, q2;
        make_q(P.dec_a2_in_w, P.dec_a2_in_b,
               s_x2[row*3], s_x2[row*3+1], s_x2[row*3+2], q0, q1, q2);
        u64 q0p = pack2(q0, q0), q1p = pack2(q1, q1), q2p = pack2(q2, q2);
        u64 aX = 0, aY = 0, aZ = 0, aL = 0;
        const double2* X2 = (const double2*)sX;
        const double2* Y2 = (const double2*)sY;
        const double2* Z2 = (const double2*)sZ;
        int i0 = half2 * 32;
        #pragma unroll 4
        for (int i = i0; i < i0 + 32; ++i) {
            double2 dx = X2[i], dy = Y2[i], dz = Z2[i];
            qstep(q0p, q1p, q2p,
                  __double_as_longlong(dx.x), __double_as_longlong(dy.x), __double_as_longlong(dz.x),
                  aX, aY, aZ, aL);
            qstep(q0p, q1p, q2p,
                  __double_as_longlong(dx.y), __double_as_longlong(dy.y), __double_as_longlong(dz.y),
                  aX, aY, aZ, aL);
        }
        float ax, ay, az, l;
        hsum4(aX, aY, aZ, aL, ax, ay, az, l);
        s_part[row*2 + half2] = make_float4(l, ax, ay, az);
    }
    __syncthreads();
    if (t < SPR) {
        float4 pa = s_part[t*2], pb = s_part[t*2+1];
        float inv = rcpf(pa.x + pb.x);
        float v0, v1, v2;
        proj3(P.dec_a2_in_w + 18, P.dec_a2_in_b + 6,
              (pa.y+pb.y)*inv, (pa.z+pb.z)*inv, (pa.w+pb.w)*inv, v0, v1, v2);
        float r0, r1, r2;
        proj3(P.dec_a2_out_w, P.dec_a2_out_b, v0, v1, v2, r0, r1, r2);
        s_R[t*3+0] = r0 + s_x2[t*3+0];
        s_R[t*3+1] = r1 + s_x2[t*3+1];
        s_R[t*3+2] = r2 + s_x2[t*3+2];
    }
    __syncthreads();
    layer_norm(s_R, s_x2, SPR, INV384, P.dec_ln1_w, P.dec_ln1_b, s_red);  // x3

    // D5: dec FFN. 2 rows {r64, r64+64} x 64 h-pairs (quarter q4), packed math.
    load_wff_pack(s_U, P.dec_lin1_w, P.dec_lin1_b, P.dec_lin2_w);
    {
        const int r = t & 63, q4 = t >> 6;
        int rowA = r, rowB = r + 64;
        u64 xA0 = pack2(s_x2[rowA*3],   s_x2[rowA*3]);
        u64 xA1 = pack2(s_x2[rowA*3+1], s_x2[rowA*3+1]);
        u64 xA2 = pack2(s_x2[rowA*3+2], s_x2[rowA*3+2]);
        u64 xB0 = pack2(s_x2[rowB*3],   s_x2[rowB*3]);
        u64 xB1 = pack2(s_x2[rowB*3+1], s_x2[rowB*3+1]);
        u64 xB2 = pack2(s_x2[rowB*3+2], s_x2[rowB*3+2]);
        float3 oA, oB;
        ffn_pack((const ulonglong2*)s_U, q4 * 64, 64,
                 xA0, xA1, xA2, xB0, xB1, xB2, oA, oB);
        float* dst = (q4 < 2) ? s_R : s_E;
        int off = (q4 & 1) * 384;
        dst[off + rowA*3+0]=oA.x; dst[off + rowA*3+1]=oA.y; dst[off + rowA*3+2]=oA.z;
        dst[off + rowB*3+0]=oB.x; dst[off + rowB*3+1]=oB.y; dst[off + rowB*3+2]=oB.z;
    }
    __syncthreads();
    if (t < SPR) {
        float db0 = P.dec_lin2_b[0], db1 = P.dec_lin2_b[1], db2 = P.dec_lin2_b[2];
        s_R[t*3+0] = s_R[t*3+0] + s_R[384+t*3+0] + s_E[t*3+0] + s_E[384+t*3+0] + db0 + s_x2[t*3+0];
        s_R[t*3+1] = s_R[t*3+1] + s_R[384+t*3+1] + s_E[t*3+1] + s_E[384+t*3+1] + db1 + s_x2[t*3+1];
        s_R[t*3+2] = s_R[t*3+2] + s_R[384+t*3+2] + s_E[t*3+2] + s_E[384+t*3+2] + db2 + s_x2[t*3+2];
    }
    __syncthreads();
    layer_norm_out(s_R, P.out + (size_t)b * SPR * 3, SPR, INV384,
                   P.dec_ln3_w, P.dec_ln3_b, s_red);
}

extern "C" void kernel_launch(void* const* d_in, const int* in_sizes, int n_in,
                              void* d_out, int out_size) {
    (void)in_sizes; (void)n_in; (void)out_size;
    Params P;
    P.X            = (const float*)d_in[0];
    P.T            = (const float*)d_in[1];
    P.enc_in_w     = (const float*)d_in[2];
    P.enc_in_b     = (const float*)d_in[3];
    P.enc_out_w    = (const float*)d_in[4];
    P.enc_out_b    = (const float*)d_in[5];
    P.enc_ln1_w    = (const float*)d_in[6];
    P.enc_ln1_b    = (const float*)d_in[7];
    P.enc_lin1_w   = (const float*)d_in[8];
    P.enc_lin1_b   = (const float*)d_in[9];
    P.enc_lin2_w   = (const float*)d_in[10];
    P.enc_lin2_b   = (const float*)d_in[11];
    P.enc_ln2_w    = (const float*)d_in[12];
    P.enc_ln2_b    = (const float*)d_in[13];
    P.dec_a1_in_w  = (const float*)d_in[14];
    P.dec_a1_in_b  = (const float*)d_in[15];
    P.dec_a1_out_w = (const float*)d_in[16];
    P.dec_a1_out_b = (const float*)d_in[17];
    P.dec_ln1_w    = (const float*)d_in[18];
    P.dec_ln1_b    = (const float*)d_in[19];
    P.dec_a2_in_w  = (const float*)d_in[20];
    P.dec_a2_in_b  = (const float*)d_in[21];
    P.dec_a2_out_w = (const float*)d_in[22];
    P.dec_a2_out_b = (const float*)d_in[23];
    P.dec_lin1_w   = (const float*)d_in[24];
    P.dec_lin1_b   = (const float*)d_in[25];
    P.dec_lin2_w   = (const float*)d_in[26];
    P.dec_lin2_b   = (const float*)d_in[27];
    P.dec_ln3_w    = (const float*)d_in[28];
    P.dec_ln3_b    = (const float*)d_in[29];
    P.out          = (float*)d_out;

    fused_transformer_kernel<<<NB, 256>>>(P);
}

// round 10
// speedup vs baseline: 1.9061x; 1.0671x over previous
#include <cuda_runtime.h>
#include <math.h>

#define NB    1024
#define SIN   256
#define SPR   128
#define HIDN  512

// 1/sqrt(3) * log2(e): fold scores into exp2 domain
#define C_SCALE 0.83294064f
// log2(e): additive causal "mask" of +1.0 in exp2 domain
#define L2E 1.4426950408889634f

typedef unsigned long long u64;

struct Params {
    const float* X;           const float* T;
    const float* enc_in_w;    const float* enc_in_b;
    const float* enc_out_w;   const float* enc_out_b;
    const float* enc_ln1_w;   const float* enc_ln1_b;
    const float* enc_lin1_w;  const float* enc_lin1_b;
    const float* enc_lin2_w;  const float* enc_lin2_b;
    const float* enc_ln2_w;   const float* enc_ln2_b;
    const float* dec_a1_in_w; const float* dec_a1_in_b;
    const float* dec_a1_out_w;const float* dec_a1_out_b;
    const float* dec_ln1_w;   const float* dec_ln1_b;
    const float* dec_a2_in_w; const float* dec_a2_in_b;
    const float* dec_a2_out_w;const float* dec_a2_out_b;
    const float* dec_lin1_w;  const float* dec_lin1_b;
    const float* dec_lin2_w;  const float* dec_lin2_b;
    const float* dec_ln3_w;   const float* dec_ln3_b;
    float* out;
};

__device__ __forceinline__ float ex2f(float x) {
    float y; asm("ex2.approx.ftz.f32 %0, %1;" : "=f"(y) : "f"(x)); return y;
}
__device__ __forceinline__ float rcpf(float x) {
    float y; asm("rcp.approx.ftz.f32 %0, %1;" : "=f"(y) : "f"(x)); return y;
}

// ---- packed f32x2 ops (Blackwell) ----
__device__ __forceinline__ u64 fma2(u64 a, u64 b, u64 c) {
    u64 d; asm("fma.rn.f32x2 %0, %1, %2, %3;" : "=l"(d) : "l"(a), "l"(b), "l"(c)); return d;
}
__device__ __forceinline__ u64 mul2(u64 a, u64 b) {
    u64 d; asm("mul.rn.f32x2 %0, %1, %2;" : "=l"(d) : "l"(a), "l"(b)); return d;
}
__device__ __forceinline__ u64 add2(u64 a, u64 b) {
    u64 d; asm("add.rn.f32x2 %0, %1, %2;" : "=l"(d) : "l"(a), "l"(b)); return d;
}
__device__ __forceinline__ u64 pack2(float lo, float hi) {
    u64 d; asm("mov.b64 %0, {%1, %2};" : "=l"(d) : "f"(lo), "f"(hi)); return d;
}
__device__ __forceinline__ void unpack2(u64 d, float& a, float& b) {
    asm("mov.b64 {%0, %1}, %2;" : "=f"(a), "=f"(b) : "l"(d));
}

// Query-pair attention step: lanes = (queryA, queryB), key broadcast in both lanes.
__device__ __forceinline__ void qpair_step(u64 qp0, u64 qp1, u64 qp2,
                                           float kx, float ky, float kz,
                                           u64& aX, u64& aY, u64& aZ, u64& aL) {
    u64 kxp = pack2(kx, kx), kyp = pack2(ky, ky), kzp = pack2(kz, kz);
    u64 d = fma2(qp2, kzp, fma2(qp1, kyp, mul2(qp0, kxp)));
    float sA, sB; unpack2(d, sA, sB);
    u64 pp = pack2(ex2f(sA), ex2f(sB));
    aX = fma2(pp, kxp, aX);
    aY = fma2(pp, kyp, aY);
    aZ = fma2(pp, kzp, aZ);
    aL = add2(aL, pp);
}
// Masked variant: reference ADDS tril(ones) -> +log2(e) in exp2 domain, per lane.
__device__ __forceinline__ void qpair_step_m(u64 qp0, u64 qp1, u64 qp2,
                                             float kx, float ky, float kz,
                                             int j, int rowA, int rowB,
                                             u64& aX, u64& aY, u64& aZ, u64& aL) {
    u64 kxp = pack2(kx, kx), kyp = pack2(ky, ky), kzp = pack2(kz, kz);
    u64 d = fma2(qp2, kzp, fma2(qp1, kyp, mul2(qp0, kxp)));
    float sA, sB; unpack2(d, sA, sB);
    sA += (j <= rowA) ? L2E : 0.f;
    sB += (j <= rowB) ? L2E : 0.f;
    u64 pp = pack2(ex2f(sA), ex2f(sB));
    aX = fma2(pp, kxp, aX);
    aY = fma2(pp, kyp, aY);
    aZ = fma2(pp, kzp, aZ);
    aL = add2(aL, pp);
}

// Fused two-value block reduction (2 barriers).
__device__ __forceinline__ void block_sum2(float& a, float& b, float* red) {
    #pragma unroll
    for (int o = 16; o; o >>= 1) {
        a += __shfl_xor_sync(0xffffffffu, a, o);
        b += __shfl_xor_sync(0xffffffffu, b, o);
    }
    int w = threadIdx.x >> 5;
    if ((threadIdx.x & 31) == 0) { red[w] = a; red[8 + w] = b; }
    __syncthreads();
    if (threadIdx.x < 16) {
        float x = red[threadIdx.x];
        x += __shfl_xor_sync(0x0000ffffu, x, 4);
        x += __shfl_xor_sync(0x0000ffffu, x, 2);
        x += __shfl_xor_sync(0x0000ffffu, x, 1);
        if ((threadIdx.x & 7) == 0) red[16 + (threadIdx.x >> 3)] = x;
    }
    __syncthreads();
    a = red[16]; b = red[17];
}

// LN over nrows*3 elems jointly; var = E[x^2]-mean^2 single pass.
__device__ __forceinline__ void layer_norm(const float* src, float* dst, int nrows,
                                           float inv_n, const float* w, const float* bb,
                                           float* red) {
    int t = threadIdx.x;
    float x0 = 0.f, x1 = 0.f, x2 = 0.f;
    if (t < nrows) { x0 = src[t*3]; x1 = src[t*3+1]; x2 = src[t*3+2]; }
    float s1 = x0 + x1 + x2;
    float s2 = fmaf(x0, x0, fmaf(x1, x1, x2 * x2));
    block_sum2(s1, s2, red);
    float mean = s1 * inv_n;
    float var  = fmaf(-mean, mean, s2 * inv_n);
    float rs = rsqrtf(var + 1e-5f);
    if (t < nrows) {
        dst[t*3+0] = (x0 - mean) * rs * w[t*3+0] + bb[t*3+0];
        dst[t*3+1] = (x1 - mean) * rs * w[t*3+1] + bb[t*3+1];
        dst[t*3+2] = (x2 - mean) * rs * w[t*3+2] + bb[t*3+2];
    }
    __syncthreads();
}

// LN writing into SoA arrays (for cross-attn keys).
__device__ __forceinline__ void layer_norm_soa(const float* src,
                                               float* dX, float* dY, float* dZ, int nrows,
                                               float inv_n, const float* w, const float* bb,
                                               float* red) {
    int t = threadIdx.x;
    float x0 = 0.f, x1 = 0.f, x2 = 0.f;
    if (t < nrows) { x0 = src[t*3]; x1 = src[t*3+1]; x2 = src[t*3+2]; }
    float s1 = x0 + x1 + x2;
    float s2 = fmaf(x0, x0, fmaf(x1, x1, x2 * x2));
    block_sum2(s1, s2, red);
    float mean = s1 * inv_n;
    float var  = fmaf(-mean, mean, s2 * inv_n);
    float rs = rsqrtf(var + 1e-5f);
    if (t < nrows) {
        dX[t] = (x0 - mean) * rs * w[t*3+0] + bb[t*3+0];
        dY[t] = (x1 - mean) * rs * w[t*3+1] + bb[t*3+1];
        dZ[t] = (x2 - mean) * rs * w[t*3+2] + bb[t*3+2];
    }
    __syncthreads();
}

// Final LN -> global.
__device__ __forceinline__ void layer_norm_out(const float* src, float* gout, int nrows,
                                               float inv_n, const float* w, const float* bb,
                                               float* red) {
    int t = threadIdx.x;
    float x0 = 0.f, x1 = 0.f, x2 = 0.f;
    if (t < nrows) { x0 = src[t*3]; x1 = src[t*3+1]; x2 = src[t*3+2]; }
    float s1 = x0 + x1 + x2;
    float s2 = fmaf(x0, x0, fmaf(x1, x1, x2 * x2));
    block_sum2(s1, s2, red);
    float mean = s1 * inv_n;
    float var  = fmaf(-mean, mean, s2 * inv_n);
    float rs = rsqrtf(var + 1e-5f);
    if (t < nrows) {
        gout[t*3+0] = (x0 - mean) * rs * w[t*3+0] + bb[t*3+0];
        gout[t*3+1] = (x1 - mean) * rs * w[t*3+1] + bb[t*3+1];
        gout[t*3+2] = (x2 - mean) * rs * w[t*3+2] + bb[t*3+2];
    }
}

__device__ __forceinline__ void proj3(const float* w, const float* bias,
                                      float x0, float x1, float x2,
                                      float& o0, float& o1, float& o2) {
    o0 = fmaf(w[0], x0, fmaf(w[1], x1, fmaf(w[2], x2, bias[0])));
    o1 = fmaf(w[3], x0, fmaf(w[4], x1, fmaf(w[5], x2, bias[1])));
    o2 = fmaf(w[6], x0, fmaf(w[7], x1, fmaf(w[8], x2, bias[2])));
}
__device__ __forceinline__ void proj3T(const float* w,
                                       float x0, float x1, float x2,
                                       float& o0, float& o1, float& o2) {
    o0 = fmaf(w[0], x0, fmaf(w[3], x1, w[6] * x2));
    o1 = fmaf(w[1], x0, fmaf(w[4], x1, w[7] * x2));
    o2 = fmaf(w[2], x0, fmaf(w[5], x1, w[8] * x2));
}
// q' = (Wk^T (Wq x + bq)) * C_SCALE; bk dropped (cancels in softmax)
__device__ __forceinline__ void make_q(const float* in_w, const float* in_b,
                                       float x0, float x1, float x2,
                                       float& q0, float& q1, float& q2) {
    float t0, t1, t2;
    proj3(in_w, in_b, x0, x1, x2, t0, t1, t2);
    proj3T(in_w + 9, t0, t1, t2, q0, q1, q2);
    q0 *= C_SCALE; q1 *= C_SCALE; q2 *= C_SCALE;
}

__device__ __forceinline__ void load_wff(float4* s_wff, const float* w1, const float* b1,
                                         const float* w2) {
    for (int h = threadIdx.x; h < HIDN; h += 256) {
        s_wff[2*h]   = make_float4(w1[h*3], w1[h*3+1], w1[h*3+2], b1[h]);
        s_wff[2*h+1] = make_float4(w2[h], w2[HIDN + h], w2[2*HIDN + h], 0.f);
    }
    __syncthreads();
}

// pos_enc row s: first 3 sin columns, invf[e] = 10000^(-2e/256)
__device__ __forceinline__ void pos3(int s, float& p0, float& p1, float& p2) {
    const float f1 = (float)0.93057204868496882;  // 10000^(-2/256)
    const float f2 = (float)0.86596432336006538;  // 10000^(-4/256)
    float a0 = (float)s;
    p0 = sinf(a0);
    p1 = sinf(a0 * f1);
    p2 = sinf(a0 * f2);
}

// One CTA = one batch. Grid caps occupancy at ~7 CTAs/SM.
__global__ void __launch_bounds__(256, 7)
fused_transformer_kernel(Params P) {
    // 16KB union s_U, time-multiplexed:
    //   attn: SoA keys (enc: sf[0..768), pT: sf[768..1152)) + partials s_U[288..800)
    //   ffn:  packed AoS weights (2 float4 per h) over s_U[0..1024)
    __shared__ __align__(16) float4 s_U[1024];
    __shared__ float s_x2[SIN * 3];
    __shared__ float s_R[SIN * 3];
    __shared__ float s_E[SIN * 3];
    __shared__ float s_red[18];

    float* const sf = (float*)s_U;
    float* const sX = sf;            // 256 floats (enc keys / enc_out keys)
    float* const sY = sf + 256;
    float* const sZ = sf + 512;
    float* const pX = sf + 768;      // 128 floats (pT keys)
    float* const pY = sf + 896;
    float* const pZ = sf + 1024;
    float4* const s_part = s_U + 288;  // attn partials (512 float4 max)

    const int b    = blockIdx.x;
    const int t    = threadIdx.x;
    const int r128 = t & 127, half2 = t >> 7;
    const int r64  = t & 63,  q4    = t >> 6;
    const float INV768 = 1.0f / 768.0f;
    const float INV384 = 1.0f / 384.0f;

    float pe0, pe1, pe2;
    pos3(t, pe0, pe1, pe2);

    // ================= ENCODER =================
    // E1: pX = X + pos_enc -> SoA keys
    {
        const float* xr = P.X + ((size_t)b * SIN + t) * 3;
        sX[t] = xr[0] + pe0;
        sY[t] = xr[1] + pe1;
        sZ[t] = xr[2] + pe2;
    }
    __syncthreads();

    // E2: self-attention. Query-pair {r128, r128+128} in f32x2 lanes x 128-key half.
    {
        int rowA = r128, rowB = r128 + 128;
        float qA0,qA1,qA2, qB0,qB1,qB2;
        make_q(P.enc_in_w, P.enc_in_b, sX[rowA], sY[rowA], sZ[rowA], qA0, qA1, qA2);
        make_q(P.enc_in_w, P.enc_in_b, sX[rowB], sY[rowB], sZ[rowB], qB0, qB1, qB2);
        u64 qp0 = pack2(qA0, qB0), qp1 = pack2(qA1, qB1), qp2 = pack2(qA2, qB2);
        u64 aX = 0, aY = 0, aZ = 0, aL = 0;
        int j0 = half2 * 128;
        #pragma unroll 4
        for (int j = j0; j < j0 + 128; ++j)
            qpair_step(qp0, qp1, qp2, sX[j], sY[j], sZ[j], aX, aY, aZ, aL);
        float lA,lB, axA,axB, ayA,ayB, azA,azB;
        unpack2(aL, lA, lB); unpack2(aX, axA, axB);
        unpack2(aY, ayA, ayB); unpack2(aZ, azA, azB);
        s_part[rowA*2 + half2] = make_float4(lA, axA, ayA, azA);
        s_part[rowB*2 + half2] = make_float4(lB, axB, ayB, azB);
    }
    __syncthreads();
    // E2b: merge halves, apply Wv then out-proj, residual
    {
        float4 pa = s_part[t*2], pb = s_part[t*2+1];
        float inv = rcpf(pa.x + pb.x);
        float v0, v1, v2;
        proj3(P.enc_in_w + 18, P.enc_in_b + 6,
              (pa.y+pb.y)*inv, (pa.z+pb.z)*inv, (pa.w+pb.w)*inv, v0, v1, v2);
        float r0, r1, r2;
        proj3(P.enc_out_w, P.enc_out_b, v0, v1, v2, r0, r1, r2);
        s_R[t*3+0] = r0 + sX[t];
        s_R[t*3+1] = r1 + sY[t];
        s_R[t*3+2] = r2 + sZ[t];
    }
    __syncthreads();
    layer_norm(s_R, s_x2, SIN, INV768, P.enc_ln1_w, P.enc_ln1_b, s_red);

    // E3: FFN. 2 rows {r128, r128+128} x 256 hidden (half2 split). (R6 form, proven.)
    load_wff(s_U, P.enc_lin1_w, P.enc_lin1_b, P.enc_lin2_w);
    {
        int rowA = r128, rowB = r128 + 128;
        float xA0=s_x2[rowA*3], xA1=s_x2[rowA*3+1], xA2=s_x2[rowA*3+2];
        float xB0=s_x2[rowB*3], xB1=s_x2[rowB*3+1], xB2=s_x2[rowB*3+2];
        float aA0=0.f,aA1=0.f,aA2=0.f, aB0=0.f,aB1=0.f,aB2=0.f;
        int h0 = half2 * 256;
        #pragma unroll 4
        for (int h = h0; h < h0 + 256; ++h) {
            float4 w1 = s_U[2*h];
            float4 w2 = s_U[2*h+1];
            float tA = fmaxf(fmaf(w1.x, xA0, fmaf(w1.y, xA1, fmaf(w1.z, xA2, w1.w))), 0.f);
            float tB = fmaxf(fmaf(w1.x, xB0, fmaf(w1.y, xB1, fmaf(w1.z, xB2, w1.w))), 0.f);
            aA0 = fmaf(tA, w2.x, aA0); aA1 = fmaf(tA, w2.y, aA1); aA2 = fmaf(tA, w2.z, aA2);
            aB0 = fmaf(tB, w2.x, aB0); aB1 = fmaf(tB, w2.y, aB1); aB2 = fmaf(tB, w2.z, aB2);
        }
        float* dst = half2 ? s_R : s_E;
        dst[rowA*3+0]=aA0; dst[rowA*3+1]=aA1; dst[rowA*3+2]=aA2;
        dst[rowB*3+0]=aB0; dst[rowB*3+1]=aB1; dst[rowB*3+2]=aB2;
    }
    __syncthreads();
    {
        float eb0 = P.enc_lin2_b[0], eb1 = P.enc_lin2_b[1], eb2 = P.enc_lin2_b[2];
        s_R[t*3+0] = s_E[t*3+0] + s_R[t*3+0] + eb0 + s_x2[t*3+0];
        s_R[t*3+1] = s_E[t*3+1] + s_R[t*3+1] + eb1 + s_x2[t*3+1];
        s_R[t*3+2] = s_E[t*3+2] + s_R[t*3+2] + eb2 + s_x2[t*3+2];
    }
    __syncthreads();
    // LN2 -> enc_out straight into SoA key arrays (for cross-attn)
    layer_norm_soa(s_R, sX, sY, sZ, SIN, INV768, P.enc_ln2_w, P.enc_ln2_b, s_red);

    // ================= DECODER =================
    // D1: pT -> SoA (pX/pY/pZ)
    if (t < SPR) {
        const float* tr = P.T + ((size_t)b * SPR + t) * 3;
        pX[t] = tr[0] + pe0;
        pY[t] = tr[1] + pe1;
        pZ[t] = tr[2] + pe2;
    }
    __syncthreads();

    // D2: dec self-attn. Query-pair {r64, r64+64} x 32-key quarter, causal +1 mask.
    {
        int rowA = r64, rowB = r64 + 64;
        float qA0,qA1,qA2, qB0,qB1,qB2;
        make_q(P.dec_a1_in_w, P.dec_a1_in_b, pX[rowA], pY[rowA], pZ[rowA], qA0, qA1, qA2);
        make_q(P.dec_a1_in_w, P.dec_a1_in_b, pX[rowB], pY[rowB], pZ[rowB], qB0, qB1, qB2);
        u64 qp0 = pack2(qA0, qB0), qp1 = pack2(qA1, qB1), qp2 = pack2(qA2, qB2);
        u64 aX = 0, aY = 0, aZ = 0, aL = 0;
        int j0 = q4 * 32;
        #pragma unroll 4
        for (int j = j0; j < j0 + 32; ++j)
            qpair_step_m(qp0, qp1, qp2, pX[j], pY[j], pZ[j], j, rowA, rowB, aX, aY, aZ, aL);
        float lA,lB, axA,axB, ayA,ayB, azA,azB;
        unpack2(aL, lA, lB); unpack2(aX, axA, axB);
        unpack2(aY, ayA, ayB); unpack2(aZ, azA, azB);
        s_part[rowA*4 + q4] = make_float4(lA, axA, ayA, azA);
        s_part[rowB*4 + q4] = make_float4(lB, axB, ayB, azB);
    }
    __syncthreads();
    if (t < SPR) {
        float4 p0 = s_part[t*4], p1 = s_part[t*4+1], p2 = s_part[t*4+2], p3 = s_part[t*4+3];
        float inv = rcpf(p0.x + p1.x + p2.x + p3.x);
        float v0, v1, v2;
        proj3(P.dec_a1_in_w + 18, P.dec_a1_in_b + 6,
              (p0.y+p1.y+p2.y+p3.y)*inv, (p0.z+p1.z+p2.z+p3.z)*inv, (p0.w+p1.w+p2.w+p3.w)*inv,
              v0, v1, v2);
        float r0, r1, r2;
        proj3(P.dec_a1_out_w, P.dec_a1_out_b, v0, v1, v2, r0, r1, r2);
        s_R[t*3+0] = r0 + pX[t];
        s_R[t*3+1] = r1 + pY[t];
        s_R[t*3+2] = r2 + pZ[t];
    }
    __syncthreads();
    layer_norm(s_R, s_x2, SPR, INV384, P.dec_ln1_w, P.dec_ln1_b, s_red);

    // D4: cross-attn. Query-pair {r64, r64+64} x 64-key quarter of enc_out keys.
    {
        int rowA = r64, rowB = r64 + 64;
        float qA0,qA1,qA2, qB0,qB1,qB2;
        make_q(P.dec_a2_in_w, P.dec_a2_in_b,
               s_x2[rowA*3], s_x2[rowA*3+1], s_x2[rowA*3+2], qA0, qA1, qA2);
        make_q(P.dec_a2_in_w, P.dec_a2_in_b,
               s_x2[rowB*3], s_x2[rowB*3+1], s_x2[rowB*3+2], qB0, qB1, qB2);
        u64 qp0 = pack2(qA0, qB0), qp1 = pack2(qA1, qB1), qp2 = pack2(qA2, qB2);
        u64 aX = 0, aY = 0, aZ = 0, aL = 0;
        int j0 = q4 * 64;
        #pragma unroll 4
        for (int j = j0; j < j0 + 64; ++j)
            qpair_step(qp0, qp1, qp2, sX[j], sY[j], sZ[j], aX, aY, aZ, aL);
        float lA,lB, axA,axB, ayA,ayB, azA,azB;
        unpack2(aL, lA, lB); unpack2(aX, axA, axB);
        unpack2(aY, ayA, ayB); unpack2(aZ, azA, azB);
        s_part[rowA*4 + q4] = make_float4(lA, axA, ayA, azA);
        s_part[rowB*4 + q4] = make_float4(lB, axB, ayB, azB);
    }
    __syncthreads();
    if (t < SPR) {
        float4 p0 = s_part[t*4], p1 = s_part[t*4+1], p2 = s_part[t*4+2], p3 = s_part[t*4+3];
        float inv = rcpf(p0.x + p1.x + p2.x + p3.x);
        float v0, v1, v2;
        proj3(P.dec_a2_in_w + 18, P.dec_a2_in_b + 6,
              (p0.y+p1.y+p2.y+p3.y)*inv, (p0.z+p1.z+p2.z+p3.z)*inv, (p0.w+p1.w+p2.w+p3.w)*inv,
              v0, v1, v2);
        float r0, r1, r2;
        proj3(P.dec_a2_out_w, P.dec_a2_out_b, v0, v1, v2, r0, r1, r2);
        s_R[t*3+0] = r0 + s_x2[t*3+0];
        s_R[t*3+1] = r1 + s_x2[t*3+1];
        s_R[t*3+2] = r2 + s_x2[t*3+2];
    }
    __syncthreads();
    layer_norm(s_R, s_x2, SPR, INV384, P.dec_ln1_w, P.dec_ln1_b, s_red);  // x3

    // D5: dec FFN. 2 rows {r64, r64+64} x 128 hidden (quarter q4). (R6 form.)
    load_wff(s_U, P.dec_lin1_w, P.dec_lin1_b, P.dec_lin2_w);
    {
        int rowA = r64, rowB = r64 + 64;
        float xA0=s_x2[rowA*3], xA1=s_x2[rowA*3+1], xA2=s_x2[rowA*3+2];
        float xB0=s_x2[rowB*3], xB1=s_x2[rowB*3+1], xB2=s_x2[rowB*3+2];
        float aA0=0.f,aA1=0.f,aA2=0.f, aB0=0.f,aB1=0.f,aB2=0.f;
        int h0 = q4 * 128;
        #pragma unroll 4
        for (int h = h0; h < h0 + 128; ++h) {
            float4 w1 = s_U[2*h];
            float4 w2 = s_U[2*h+1];
            float tA = fmaxf(fmaf(w1.x, xA0, fmaf(w1.y, xA1, fmaf(w1.z, xA2, w1.w))), 0.f);
            float tB = fmaxf(fmaf(w1.x, xB0, fmaf(w1.y, xB1, fmaf(w1.z, xB2, w1.w))), 0.f);
            aA0 = fmaf(tA, w2.x, aA0); aA1 = fmaf(tA, w2.y, aA1); aA2 = fmaf(tA, w2.z, aA2);
            aB0 = fmaf(tB, w2.x, aB0); aB1 = fmaf(tB, w2.y, aB1); aB2 = fmaf(tB, w2.z, aB2);
        }
        float* dst = (q4 < 2) ? s_R : s_E;
        int off = (q4 & 1) * 384;
        dst[off + rowA*3+0]=aA0; dst[off + rowA*3+1]=aA1; dst[off + rowA*3+2]=aA2;
        dst[off + rowB*3+0]=aB0; dst[off + rowB*3+1]=aB1; dst[off + rowB*3+2]=aB2;
    }
    __syncthreads();
    if (t < SPR) {
        float db0 = P.dec_lin2_b[0], db1 = P.dec_lin2_b[1], db2 = P.dec_lin2_b[2];
        s_R[t*3+0] = s_R[t*3+0] + s_R[384+t*3+0] + s_E[t*3+0] + s_E[384+t*3+0] + db0 + s_x2[t*3+0];
        s_R[t*3+1] = s_R[t*3+1] + s_R[384+t*3+1] + s_E[t*3+1] + s_E[384+t*3+1] + db1 + s_x2[t*3+1];
        s_R[t*3+2] = s_R[t*3+2] + s_R[384+t*3+2] + s_E[t*3+2] + s_E[384+t*3+2] + db2 + s_x2[t*3+2];
    }
    __syncthreads();
    layer_norm_out(s_R, P.out + (size_t)b * SPR * 3, SPR, INV384,
                   P.dec_ln3_w, P.dec_ln3_b, s_red);
}

extern "C" void kernel_launch(void* const* d_in, const int* in_sizes, int n_in,
                              void* d_out, int out_size) {
    (void)in_sizes; (void)n_in; (void)out_size;
    Params P;
    P.X            = (const float*)d_in[0];
    P.T            = (const float*)d_in[1];
    P.enc_in_w     = (const float*)d_in[2];
    P.enc_in_b     = (const float*)d_in[3];
    P.enc_out_w    = (const float*)d_in[4];
    P.enc_out_b    = (const float*)d_in[5];
    P.enc_ln1_w    = (const float*)d_in[6];
    P.enc_ln1_b    = (const float*)d_in[7];
    P.enc_lin1_w   = (const float*)d_in[8];
    P.enc_lin1_b   = (const float*)d_in[9];
    P.enc_lin2_w   = (const float*)d_in[10];
    P.enc_lin2_b   = (const float*)d_in[11];
    P.enc_ln2_w    = (const float*)d_in[12];
    P.enc_ln2_b    = (const float*)d_in[13];
    P.dec_a1_in_w  = (const float*)d_in[14];
    P.dec_a1_in_b  = (const float*)d_in[15];
    P.dec_a1_out_w = (const float*)d_in[16];
    P.dec_a1_out_b = (const float*)d_in[17];
    P.dec_ln1_w    = (const float*)d_in[18];
    P.dec_ln1_b    = (const float*)d_in[19];
    P.dec_a2_in_w  = (const float*)d_in[20];
    P.dec_a2_in_b  = (const float*)d_in[21];
    P.dec_a2_out_w = (const float*)d_in[22];
    P.dec_a2_out_b = (const float*)d_in[23];
    P.dec_lin1_w   = (const float*)d_in[24];
    P.dec_lin1_b   = (const float*)d_in[25];
    P.dec_lin2_w   = (const float*)d_in[26];
    P.dec_lin2_b   = (const float*)d_in[27];
    P.dec_ln3_w    = (const float*)d_in[28];
    P.dec_ln3_b    = (const float*)d_in[29];
    P.out          = (float*)d_out;

    fused_transformer_kernel<<<NB, 256>>>(P);
}

// round 11
// speedup vs baseline: 1.9407x; 1.0182x over previous
#include <cuda_runtime.h>
#include <math.h>

#define NB    1024
#define SIN   256
#define SPR   128
#define HIDN  512

// 1/sqrt(3) * log2(e): fold scores into exp2 domain
#define C_SCALE 0.83294064f
// log2(e): additive causal "mask" of +1.0 in exp2 domain
#define L2E 1.4426950408889634f

typedef unsigned long long u64;

struct Params {
    const float* X;           const float* T;
    const float* enc_in_w;    const float* enc_in_b;
    const float* enc_out_w;   const float* enc_out_b;
    const float* enc_ln1_w;   const float* enc_ln1_b;
    const float* enc_lin1_w;  const float* enc_lin1_b;
    const float* enc_lin2_w;  const float* enc_lin2_b;
    const float* enc_ln2_w;   const float* enc_ln2_b;
    const float* dec_a1_in_w; const float* dec_a1_in_b;
    const float* dec_a1_out_w;const float* dec_a1_out_b;
    const float* dec_ln1_w;   const float* dec_ln1_b;
    const float* dec_a2_in_w; const float* dec_a2_in_b;
    const float* dec_a2_out_w;const float* dec_a2_out_b;
    const float* dec_lin1_w;  const float* dec_lin1_b;
    const float* dec_lin2_w;  const float* dec_lin2_b;
    const float* dec_ln3_w;   const float* dec_ln3_b;
    float* out;
};

__device__ __forceinline__ float ex2f(float x) {
    float y; asm("ex2.approx.ftz.f32 %0, %1;" : "=f"(y) : "f"(x)); return y;
}
__device__ __forceinline__ float rcpf(float x) {
    float y; asm("rcp.approx.ftz.f32 %0, %1;" : "=f"(y) : "f"(x)); return y;
}

// ---- packed f32x2 ops (Blackwell) ----
__device__ __forceinline__ u64 fma2(u64 a, u64 b, u64 c) {
    u64 d; asm("fma.rn.f32x2 %0, %1, %2, %3;" : "=l"(d) : "l"(a), "l"(b), "l"(c)); return d;
}
__device__ __forceinline__ u64 mul2(u64 a, u64 b) {
    u64 d; asm("mul.rn.f32x2 %0, %1, %2;" : "=l"(d) : "l"(a), "l"(b)); return d;
}
__device__ __forceinline__ u64 add2(u64 a, u64 b) {
    u64 d; asm("add.rn.f32x2 %0, %1, %2;" : "=l"(d) : "l"(a), "l"(b)); return d;
}
__device__ __forceinline__ u64 pack2(float lo, float hi) {
    u64 d; asm("mov.b64 %0, {%1, %2};" : "=l"(d) : "f"(lo), "f"(hi)); return d;
}
__device__ __forceinline__ void unpack2(u64 d, float& a, float& b) {
    asm("mov.b64 {%0, %1}, %2;" : "=f"(a), "=f"(b) : "l"(d));
}
__device__ __forceinline__ float hadd2(u64 d) {
    float a, b; unpack2(d, a, b); return a + b;
}

// Key-pair attention step (R6): lanes = 2 keys vs 1 broadcast query.
__device__ __forceinline__ void qstep(u64 q0p, u64 q1p, u64 q2p,
                                      u64 xp, u64 yp, u64 zp,
                                      u64& aX, u64& aY, u64& aZ, u64& aL) {
    u64 d = fma2(q2p, zp, fma2(q1p, yp, mul2(q0p, xp)));
    float s0, s1; unpack2(d, s0, s1);
    u64 pp = pack2(ex2f(s0), ex2f(s1));
    aX = fma2(pp, xp, aX);
    aY = fma2(pp, yp, aY);
    aZ = fma2(pp, zp, aZ);
    aL = add2(aL, pp);
}
__device__ __forceinline__ void hsum4(u64 aX, u64 aY, u64 aZ, u64 aL,
                                      float& x, float& y, float& z, float& l) {
    x = hadd2(aX); y = hadd2(aY); z = hadd2(aZ); l = hadd2(aL);
}

// Query-pair step: lanes = (queryA, queryB), key broadcast in both lanes.
__device__ __forceinline__ void qpair_step(u64 qp0, u64 qp1, u64 qp2,
                                           float kx, float ky, float kz,
                                           u64& aX, u64& aY, u64& aZ, u64& aL) {
    u64 kxp = pack2(kx, kx), kyp = pack2(ky, ky), kzp = pack2(kz, kz);
    u64 d = fma2(qp2, kzp, fma2(qp1, kyp, mul2(qp0, kxp)));
    float sA, sB; unpack2(d, sA, sB);
    u64 pp = pack2(ex2f(sA), ex2f(sB));
    aX = fma2(pp, kxp, aX);
    aY = fma2(pp, kyp, aY);
    aZ = fma2(pp, kzp, aZ);
    aL = add2(aL, pp);
}
// Masked: reference ADDS tril(ones) -> +log2(e) in exp2 domain, per lane.
__device__ __forceinline__ void qpair_step_m(u64 qp0, u64 qp1, u64 qp2,
                                             float kx, float ky, float kz,
                                             int j, int rowA, int rowB,
                                             u64& aX, u64& aY, u64& aZ, u64& aL) {
    u64 kxp = pack2(kx, kx), kyp = pack2(ky, ky), kzp = pack2(kz, kz);
    u64 d = fma2(qp2, kzp, fma2(qp1, kyp, mul2(qp0, kxp)));
    float sA, sB; unpack2(d, sA, sB);
    sA += (j <= rowA) ? L2E : 0.f;
    sB += (j <= rowB) ? L2E : 0.f;
    u64 pp = pack2(ex2f(sA), ex2f(sB));
    aX = fma2(pp, kxp, aX);
    aY = fma2(pp, kyp, aY);
    aZ = fma2(pp, kzp, aZ);
    aL = add2(aL, pp);
}

// Fused two-value block reduction (2 barriers).
__device__ __forceinline__ void block_sum2(float& a, float& b, float* red) {
    #pragma unroll
    for (int o = 16; o; o >>= 1) {
        a += __shfl_xor_sync(0xffffffffu, a, o);
        b += __shfl_xor_sync(0xffffffffu, b, o);
    }
    int w = threadIdx.x >> 5;
    if ((threadIdx.x & 31) == 0) { red[w] = a; red[8 + w] = b; }
    __syncthreads();
    if (threadIdx.x < 16) {
        float x = red[threadIdx.x];
        x += __shfl_xor_sync(0x0000ffffu, x, 4);
        x += __shfl_xor_sync(0x0000ffffu, x, 2);
        x += __shfl_xor_sync(0x0000ffffu, x, 1);
        if ((threadIdx.x & 7) == 0) red[16 + (threadIdx.x >> 3)] = x;
    }
    __syncthreads();
    a = red[16]; b = red[17];
}

__device__ __forceinline__ void proj3(const float* w, const float* bias,
                                      float x0, float x1, float x2,
                                      float& o0, float& o1, float& o2) {
    o0 = fmaf(w[0], x0, fmaf(w[1], x1, fmaf(w[2], x2, bias[0])));
    o1 = fmaf(w[3], x0, fmaf(w[4], x1, fmaf(w[5], x2, bias[1])));
    o2 = fmaf(w[6], x0, fmaf(w[7], x1, fmaf(w[8], x2, bias[2])));
}
__device__ __forceinline__ void proj3T(const float* w,
                                       float x0, float x1, float x2,
                                       float& o0, float& o1, float& o2) {
    o0 = fmaf(w[0], x0, fmaf(w[3], x1, w[6] * x2));
    o1 = fmaf(w[1], x0, fmaf(w[4], x1, w[7] * x2));
    o2 = fmaf(w[2], x0, fmaf(w[5], x1, w[8] * x2));
}
// q' = (Wk^T (Wq x + bq)) * C_SCALE; bk dropped (cancels in softmax)
__device__ __forceinline__ void make_q(const float* in_w, const float* in_b,
                                       float x0, float x1, float x2,
                                       float& q0, float& q1, float& q2) {
    float t0, t1, t2;
    proj3(in_w, in_b, x0, x1, x2, t0, t1, t2);
    proj3T(in_w + 9, t0, t1, t2, q0, q1, q2);
    q0 *= C_SCALE; q1 *= C_SCALE; q2 *= C_SCALE;
}

// LN over nrows*3 elems jointly; var = E[x^2]-mean^2 single pass.
__device__ __forceinline__ void layer_norm(const float* src, float* dst, int nrows,
                                           float inv_n, const float* w, const float* bb,
                                           float* red) {
    int t = threadIdx.x;
    float x0 = 0.f, x1 = 0.f, x2 = 0.f;
    if (t < nrows) { x0 = src[t*3]; x1 = src[t*3+1]; x2 = src[t*3+2]; }
    float s1 = x0 + x1 + x2;
    float s2 = fmaf(x0, x0, fmaf(x1, x1, x2 * x2));
    block_sum2(s1, s2, red);
    float mean = s1 * inv_n;
    float var  = fmaf(-mean, mean, s2 * inv_n);
    float rs = rsqrtf(var + 1e-5f);
    if (t < nrows) {
        dst[t*3+0] = (x0 - mean) * rs * w[t*3+0] + bb[t*3+0];
        dst[t*3+1] = (x1 - mean) * rs * w[t*3+1] + bb[t*3+1];
        dst[t*3+2] = (x2 - mean) * rs * w[t*3+2] + bb[t*3+2];
    }
    __syncthreads();
}

// LN writing into SoA arrays (for cross-attn keys).
__device__ __forceinline__ void layer_norm_soa(const float* src,
                                               float* dX, float* dY, float* dZ, int nrows,
                                               float inv_n, const float* w, const float* bb,
                                               float* red) {
    int t = threadIdx.x;
    float x0 = 0.f, x1 = 0.f, x2 = 0.f;
    if (t < nrows) { x0 = src[t*3]; x1 = src[t*3+1]; x2 = src[t*3+2]; }
    float s1 = x0 + x1 + x2;
    float s2 = fmaf(x0, x0, fmaf(x1, x1, x2 * x2));
    block_sum2(s1, s2, red);
    float mean = s1 * inv_n;
    float var  = fmaf(-mean, mean, s2 * inv_n);
    float rs = rsqrtf(var + 1e-5f);
    if (t < nrows) {
        dX[t] = (x0 - mean) * rs * w[t*3+0] + bb[t*3+0];
        dY[t] = (x1 - mean) * rs * w[t*3+1] + bb[t*3+1];
        dZ[t] = (x2 - mean) * rs * w[t*3+2] + bb[t*3+2];
    }
    __syncthreads();
}

// LN + fused query precompute: writes LN result to dst AND q = make_q(qw,qb,LN-out)
// into SoA arrays (deduplicates per-query projection for the following attention).
__device__ __forceinline__ void layer_norm_q(const float* src, float* dst,
                                             float* qX, float* qY, float* qZ,
                                             const float* qw, const float* qb,
                                             int nrows, float inv_n,
                                             const float* w, const float* bb, float* red) {
    int t = threadIdx.x;
    float x0 = 0.f, x1 = 0.f, x2 = 0.f;
    if (t < nrows) { x0 = src[t*3]; x1 = src[t*3+1]; x2 = src[t*3+2]; }
    float s1 = x0 + x1 + x2;
    float s2 = fmaf(x0, x0, fmaf(x1, x1, x2 * x2));
    block_sum2(s1, s2, red);
    float mean = s1 * inv_n;
    float var  = fmaf(-mean, mean, s2 * inv_n);
    float rs = rsqrtf(var + 1e-5f);
    if (t < nrows) {
        float o0 = (x0 - mean) * rs * w[t*3+0] + bb[t*3+0];
        float o1 = (x1 - mean) * rs * w[t*3+1] + bb[t*3+1];
        float o2 = (x2 - mean) * rs * w[t*3+2] + bb[t*3+2];
        dst[t*3+0] = o0; dst[t*3+1] = o1; dst[t*3+2] = o2;
        float q0, q1, q2;
        make_q(qw, qb, o0, o1, o2, q0, q1, q2);
        qX[t] = q0; qY[t] = q1; qZ[t] = q2;
    }
    __syncthreads();
}

// Final LN -> global.
__device__ __forceinline__ void layer_norm_out(const float* src, float* gout, int nrows,
                                               float inv_n, const float* w, const float* bb,
                                               float* red) {
    int t = threadIdx.x;
    float x0 = 0.f, x1 = 0.f, x2 = 0.f;
    if (t < nrows) { x0 = src[t*3]; x1 = src[t*3+1]; x2 = src[t*3+2]; }
    float s1 = x0 + x1 + x2;
    float s2 = fmaf(x0, x0, fmaf(x1, x1, x2 * x2));
    block_sum2(s1, s2, red);
    float mean = s1 * inv_n;
    float var  = fmaf(-mean, mean, s2 * inv_n);
    float rs = rsqrtf(var + 1e-5f);
    if (t < nrows) {
        gout[t*3+0] = (x0 - mean) * rs * w[t*3+0] + bb[t*3+0];
        gout[t*3+1] = (x1 - mean) * rs * w[t*3+1] + bb[t*3+1];
        gout[t*3+2] = (x2 - mean) * rs * w[t*3+2] + bb[t*3+2];
    }
}

__device__ __forceinline__ void load_wff(float4* s_wff, const float* w1, const float* b1,
                                         const float* w2) {
    for (int h = threadIdx.x; h < HIDN; h += 256) {
        s_wff[2*h]   = make_float4(w1[h*3], w1[h*3+1], w1[h*3+2], b1[h]);
        s_wff[2*h+1] = make_float4(w2[h], w2[HIDN + h], w2[2*HIDN + h], 0.f);
    }
    __syncthreads();
}

// pos_enc row s: first 3 sin columns, invf[e] = 10000^(-2e/256)
__device__ __forceinline__ void pos3(int s, float& p0, float& p1, float& p2) {
    const float f1 = (float)0.93057204868496882;  // 10000^(-2/256)
    const float f2 = (float)0.86596432336006538;  // 10000^(-4/256)
    float a0 = (float)s;
    p0 = sinf(a0);
    p1 = sinf(a0 * f1);
    p2 = sinf(a0 * f2);
}

// One CTA = one batch. Grid caps occupancy at ~7 CTAs/SM.
__global__ void __launch_bounds__(256, 7)
fused_transformer_kernel(Params P) {
    // 16KB union s_U (float view sf[0..4096)), time-multiplexed:
    //   attn: enc keys SoA [0..768) | pT SoA [768..1152) | partials f4[288..800)
    //         | q SoA [3200..3584)
    //   ffn:  packed AoS weights (2 float4 per h) over s_U[0..1024)
    __shared__ __align__(16) float4 s_U[1024];
    __shared__ float s_x2[SIN * 3];
    __shared__ float s_R[SIN * 3];
    __shared__ float s_E[SIN * 3];
    __shared__ float s_red[18];

    float* const sf = (float*)s_U;
    float* const sX = sf;            // 256 floats (enc keys / enc_out keys)
    float* const sY = sf + 256;
    float* const sZ = sf + 512;
    float* const pX = sf + 768;      // 128 floats (pT keys)
    float* const pY = sf + 896;
    float* const pZ = sf + 1024;
    float4* const s_part = s_U + 288;  // attn partials (512 float4)
    float* const qQX = sf + 3200;    // 128 floats: precomputed decoder queries
    float* const qQY = sf + 3328;
    float* const qQZ = sf + 3456;

    const int b    = blockIdx.x;
    const int t    = threadIdx.x;
    const int r128 = t & 127, half2 = t >> 7;
    const int r64  = t & 63,  q4    = t >> 6;
    const float INV768 = 1.0f / 768.0f;
    const float INV384 = 1.0f / 384.0f;

    float pe0, pe1, pe2;
    pos3(t, pe0, pe1, pe2);

    // ================= ENCODER =================
    // E1: pX = X + pos_enc -> SoA keys
    {
        const float* xr = P.X + ((size_t)b * SIN + t) * 3;
        sX[t] = xr[0] + pe0;
        sY[t] = xr[1] + pe1;
        sZ[t] = xr[2] + pe2;
    }
    __syncthreads();

    // E2: self-attention. 1 query (row t) x all 256 keys, packed key-pairs (R6).
    {
        float x0 = sX[t], x1 = sY[t], x2v = sZ[t];
        float q0, q1, q2;
        make_q(P.enc_in_w, P.enc_in_b, x0, x1, x2v, q0, q1, q2);
        u64 q0p = pack2(q0, q0), q1p = pack2(q1, q1), q2p = pack2(q2, q2);
        u64 aX = 0, aY = 0, aZ = 0, aL = 0;
        const double2* X2 = (const double2*)sX;
        const double2* Y2 = (const double2*)sY;
        const double2* Z2 = (const double2*)sZ;
        #pragma unroll 4
        for (int i = 0; i < 64; ++i) {
            double2 dx = X2[i], dy = Y2[i], dz = Z2[i];
            qstep(q0p, q1p, q2p,
                  __double_as_longlong(dx.x), __double_as_longlong(dy.x), __double_as_longlong(dz.x),
                  aX, aY, aZ, aL);
            qstep(q0p, q1p, q2p,
                  __double_as_longlong(dx.y), __double_as_longlong(dy.y), __double_as_longlong(dz.y),
                  aX, aY, aZ, aL);
        }
        float ax, ay, az, l;
        hsum4(aX, aY, aZ, aL, ax, ay, az, l);
        float inv = rcpf(l);
        float v0, v1, v2;
        proj3(P.enc_in_w + 18, P.enc_in_b + 6, ax*inv, ay*inv, az*inv, v0, v1, v2);
        float r0, r1, r2;
        proj3(P.enc_out_w, P.enc_out_b, v0, v1, v2, r0, r1, r2);
        s_R[t*3+0] = r0 + x0;
        s_R[t*3+1] = r1 + x1;
        s_R[t*3+2] = r2 + x2v;
    }
    __syncthreads();
    layer_norm(s_R, s_x2, SIN, INV768, P.enc_ln1_w, P.enc_ln1_b, s_red);

    // E3: FFN. 2 rows {r128, r128+128} x 256 hidden (half2 split). (R6 form.)
    load_wff(s_U, P.enc_lin1_w, P.enc_lin1_b, P.enc_lin2_w);
    {
        int rowA = r128, rowB = r128 + 128;
        float xA0=s_x2[rowA*3], xA1=s_x2[rowA*3+1], xA2=s_x2[rowA*3+2];
        float xB0=s_x2[rowB*3], xB1=s_x2[rowB*3+1], xB2=s_x2[rowB*3+2];
        float aA0=0.f,aA1=0.f,aA2=0.f, aB0=0.f,aB1=0.f,aB2=0.f;
        int h0 = half2 * 256;
        #pragma unroll 4
        for (int h = h0; h < h0 + 256; ++h) {
            float4 w1 = s_U[2*h];
            float4 w2 = s_U[2*h+1];
            float tA = fmaxf(fmaf(w1.x, xA0, fmaf(w1.y, xA1, fmaf(w1.z, xA2, w1.w))), 0.f);
            float tB = fmaxf(fmaf(w1.x, xB0, fmaf(w1.y, xB1, fmaf(w1.z, xB2, w1.w))), 0.f);
            aA0 = fmaf(tA, w2.x, aA0); aA1 = fmaf(tA, w2.y, aA1); aA2 = fmaf(tA, w2.z, aA2);
            aB0 = fmaf(tB, w2.x, aB0); aB1 = fmaf(tB, w2.y, aB1); aB2 = fmaf(tB, w2.z, aB2);
        }
        float* dst = half2 ? s_R : s_E;
        dst[rowA*3+0]=aA0; dst[rowA*3+1]=aA1; dst[rowA*3+2]=aA2;
        dst[rowB*3+0]=aB0; dst[rowB*3+1]=aB1; dst[rowB*3+2]=aB2;
    }
    __syncthreads();
    {
        float eb0 = P.enc_lin2_b[0], eb1 = P.enc_lin2_b[1], eb2 = P.enc_lin2_b[2];
        s_R[t*3+0] = s_E[t*3+0] + s_R[t*3+0] + eb0 + s_x2[t*3+0];
        s_R[t*3+1] = s_E[t*3+1] + s_R[t*3+1] + eb1 + s_x2[t*3+1];
        s_R[t*3+2] = s_E[t*3+2] + s_R[t*3+2] + eb2 + s_x2[t*3+2];
    }
    __syncthreads();

    // ================= fused: LN2 -> enc_out keys  +  pT + q_self precompute =====
    // pT region and q region are disjoint from LN2's outputs; LN2's internal +
    // trailing barriers cover all of it.
    if (t < SPR) {
        const float* tr = P.T + ((size_t)b * SPR + t) * 3;
        float x0 = tr[0] + pe0, x1 = tr[1] + pe1, x2v = tr[2] + pe2;
        pX[t] = x0; pY[t] = x1; pZ[t] = x2v;
        float q0, q1, q2;
        make_q(P.dec_a1_in_w, P.dec_a1_in_b, x0, x1, x2v, q0, q1, q2);
        qQX[t] = q0; qQY[t] = q1; qQZ[t] = q2;
    }
    layer_norm_soa(s_R, sX, sY, sZ, SIN, INV768, P.enc_ln2_w, P.enc_ln2_b, s_red);

    // ================= DECODER =================
    // D2: dec self-attn. Query-pair {r64, r64+64} (q from smem) x 32-key quarter.
    {
        int rowA = r64, rowB = r64 + 64;
        u64 qp0 = pack2(qQX[rowA], qQX[rowB]);
        u64 qp1 = pack2(qQY[rowA], qQY[rowB]);
        u64 qp2 = pack2(qQZ[rowA], qQZ[rowB]);
        u64 aX = 0, aY = 0, aZ = 0, aL = 0;
        int j0 = q4 * 32;
        #pragma unroll 4
        for (int j = j0; j < j0 + 32; ++j)
            qpair_step_m(qp0, qp1, qp2, pX[j], pY[j], pZ[j], j, rowA, rowB, aX, aY, aZ, aL);
        float lA,lB, axA,axB, ayA,ayB, azA,azB;
        unpack2(aL, lA, lB); unpack2(aX, axA, axB);
        unpack2(aY, ayA, ayB); unpack2(aZ, azA, azB);
        s_part[rowA*4 + q4] = make_float4(lA, axA, ayA, azA);
        s_part[rowB*4 + q4] = make_float4(lB, axB, ayB, azB);
    }
    __syncthreads();
    if (t < SPR) {
        float4 p0 = s_part[t*4], p1 = s_part[t*4+1], p2 = s_part[t*4+2], p3 = s_part[t*4+3];
        float inv = rcpf(p0.x + p1.x + p2.x + p3.x);
        float v0, v1, v2;
        proj3(P.dec_a1_in_w + 18, P.dec_a1_in_b + 6,
              (p0.y+p1.y+p2.y+p3.y)*inv, (p0.z+p1.z+p2.z+p3.z)*inv, (p0.w+p1.w+p2.w+p3.w)*inv,
              v0, v1, v2);
        float r0, r1, r2;
        proj3(P.dec_a1_out_w, P.dec_a1_out_b, v0, v1, v2, r0, r1, r2);
        s_R[t*3+0] = r0 + pX[t];
        s_R[t*3+1] = r1 + pY[t];
        s_R[t*3+2] = r2 + pZ[t];
    }
    __syncthreads();
    // LN -> x2, fused with cross-query precompute q = make_q(dec_a2, x2)
    layer_norm_q(s_R, s_x2, qQX, qQY, qQZ, P.dec_a2_in_w, P.dec_a2_in_b,
                 SPR, INV384, P.dec_ln1_w, P.dec_ln1_b, s_red);

    // D4: cross-attn. Query-pair {r64, r64+64} (q from smem) x 64-key quarter.
    {
        int rowA = r64, rowB = r64 + 64;
        u64 qp0 = pack2(qQX[rowA], qQX[rowB]);
        u64 qp1 = pack2(qQY[rowA], qQY[rowB]);
        u64 qp2 = pack2(qQZ[rowA], qQZ[rowB]);
        u64 aX = 0, aY = 0, aZ = 0, aL = 0;
        int j0 = q4 * 64;
        #pragma unroll 4
        for (int j = j0; j < j0 + 64; ++j)
            qpair_step(qp0, qp1, qp2, sX[j], sY[j], sZ[j], aX, aY, aZ, aL);
        float lA,lB, axA,axB, ayA,ayB, azA,azB;
        unpack2(aL, lA, lB); unpack2(aX, axA, axB);
        unpack2(aY, ayA, ayB); unpack2(aZ, azA, azB);
        s_part[rowA*4 + q4] = make_float4(lA, axA, ayA, azA);
        s_part[rowB*4 + q4] = make_float4(lB, axB, ayB, azB);
    }
    __syncthreads();
    if (t < SPR) {
        float4 p0 = s_part[t*4], p1 = s_part[t*4+1], p2 = s_part[t*4+2], p3 = s_part[t*4+3];
        float inv = rcpf(p0.x + p1.x + p2.x + p3.x);
        float v0, v1, v2;
        proj3(P.dec_a2_in_w + 18, P.dec_a2_in_b + 6,
              (p0.y+p1.y+p2.y+p3.y)*inv, (p0.z+p1.z+p2.z+p3.z)*inv, (p0.w+p1.w+p2.w+p3.w)*inv,
              v0, v1, v2);
        float r0, r1, r2;
        proj3(P.dec_a2_out_w, P.dec_a2_out_b, v0, v1, v2, r0, r1, r2);
        s_R[t*3+0] = r0 + s_x2[t*3+0];
        s_R[t*3+1] = r1 + s_x2[t*3+1];
        s_R[t*3+2] = r2 + s_x2[t*3+2];
    }
    __syncthreads();
    layer_norm(s_R, s_x2, SPR, INV384, P.dec_ln1_w, P.dec_ln1_b, s_red);  // x3

    // D5: dec FFN. 2 rows {r64, r64+64} x 128 hidden (quarter q4). (R6 form.)
    load_wff(s_U, P.dec_lin1_w, P.dec_lin1_b, P.dec_lin2_w);
    {
        int rowA = r64, rowB = r64 + 64;
        float xA0=s_x2[rowA*3], xA1=s_x2[rowA*3+1], xA2=s_x2[rowA*3+2];
        float xB0=s_x2[rowB*3], xB1=s_x2[rowB*3+1], xB2=s_x2[rowB*3+2];
        float aA0=0.f,aA1=0.f,aA2=0.f, aB0=0.f,aB1=0.f,aB2=0.f;
        int h0 = q4 * 128;
        #pragma unroll 4
        for (int h = h0; h < h0 + 128; ++h) {
            float4 w1 = s_U[2*h];
            float4 w2 = s_U[2*h+1];
            float tA = fmaxf(fmaf(w1.x, xA0, fmaf(w1.y, xA1, fmaf(w1.z, xA2, w1.w))), 0.f);
            float tB = fmaxf(fmaf(w1.x, xB0, fmaf(w1.y, xB1, fmaf(w1.z, xB2, w1.w))), 0.f);
            aA0 = fmaf(tA, w2.x, aA0); aA1 = fmaf(tA, w2.y, aA1); aA2 = fmaf(tA, w2.z, aA2);
            aB0 = fmaf(tB, w2.x, aB0); aB1 = fmaf(tB, w2.y, aB1); aB2 = fmaf(tB, w2.z, aB2);
        }
        float* dst = (q4 < 2) ? s_R : s_E;
        int off = (q4 & 1) * 384;
        dst[off + rowA*3+0]=aA0; dst[off + rowA*3+1]=aA1; dst[off + rowA*3+2]=aA2;
        dst[off + rowB*3+0]=aB0; dst[off + rowB*3+1]=aB1; dst[off + rowB*3+2]=aB2;
    }
    __syncthreads();
    if (t < SPR) {
        float db0 = P.dec_lin2_b[0], db1 = P.dec_lin2_b[1], db2 = P.dec_lin2_b[2];
        s_R[t*3+0] = s_R[t*3+0] + s_R[384+t*3+0] + s_E[t*3+0] + s_E[384+t*3+0] + db0 + s_x2[t*3+0];
        s_R[t*3+1] = s_R[t*3+1] + s_R[384+t*3+1] + s_E[t*3+1] + s_E[384+t*3+1] + db1 + s_x2[t*3+1];
        s_R[t*3+2] = s_R[t*3+2] + s_R[384+t*3+2] + s_E[t*3+2] + s_E[384+t*3+2] + db2 + s_x2[t*3+2];
    }
    __syncthreads();
    layer_norm_out(s_R, P.out + (size_t)b * SPR * 3, SPR, INV384,
                   P.dec_ln3_w, P.dec_ln3_b, s_red);
}

extern "C" void kernel_launch(void* const* d_in, const int* in_sizes, int n_in,
                              void* d_out, int out_size) {
    (void)in_sizes; (void)n_in; (void)out_size;
    Params P;
    P.X            = (const float*)d_in[0];
    P.T            = (const float*)d_in[1];
    P.enc_in_w     = (const float*)d_in[2];
    P.enc_in_b     = (const float*)d_in[3];
    P.enc_out_w    = (const float*)d_in[4];
    P.enc_out_b    = (const float*)d_in[5];
    P.enc_ln1_w    = (const float*)d_in[6];
    P.enc_ln1_b    = (const float*)d_in[7];
    P.enc_lin1_w   = (const float*)d_in[8];
    P.enc_lin1_b   = (const float*)d_in[9];
    P.enc_lin2_w   = (const float*)d_in[10];
    P.enc_lin2_b   = (const float*)d_in[11];
    P.enc_ln2_w    = (const float*)d_in[12];
    P.enc_ln2_b    = (const float*)d_in[13];
    P.dec_a1_in_w  = (const float*)d_in[14];
    P.dec_a1_in_b  = (const float*)d_in[15];
    P.dec_a1_out_w = (const float*)d_in[16];
    P.dec_a1_out_b = (const float*)d_in[17];
    P.dec_ln1_w    = (const float*)d_in[18];
    P.dec_ln1_b    = (const float*)d_in[19];
    P.dec_a2_in_w  = (const float*)d_in[20];
    P.dec_a2_in_b  = (const float*)d_in[21];
    P.dec_a2_out_w = (const float*)d_in[22];
    P.dec_a2_out_b = (const float*)d_in[23];
    P.dec_lin1_w   = (const float*)d_in[24];
    P.dec_lin1_b   = (const float*)d_in[25];
    P.dec_lin2_w   = (const float*)d_in[26];
    P.dec_lin2_b   = (const float*)d_in[27];
    P.dec_ln3_w    = (const float*)d_in[28];
    P.dec_ln3_b    = (const float*)d_in[29];
    P.out          = (float*)d_out;

    fused_transformer_kernel<<<NB, 256>>>(P);
}

// round 12
// speedup vs baseline: 1.9791x; 1.0197x over previous
#include <cuda_runtime.h>
#include <math.h>

#define NB    1024
#define SIN   256
#define SPR   128
#define HIDN  512

// 1/sqrt(3) * log2(e): fold scores into exp2 domain
#define C_SCALE 0.83294064f
// log2(e): additive causal "mask" of +1.0 in exp2 domain
#define L2E 1.4426950408889634f

typedef unsigned long long u64;

struct Params {
    const float* X;           const float* T;
    const float* enc_in_w;    const float* enc_in_b;
    const float* enc_out_w;   const float* enc_out_b;
    const float* enc_ln1_w;   const float* enc_ln1_b;
    const float* enc_lin1_w;  const float* enc_lin1_b;
    const float* enc_lin2_w;  const float* enc_lin2_b;
    const float* enc_ln2_w;   const float* enc_ln2_b;
    const float* dec_a1_in_w; const float* dec_a1_in_b;
    const float* dec_a1_out_w;const float* dec_a1_out_b;
    const float* dec_ln1_w;   const float* dec_ln1_b;
    const float* dec_a2_in_w; const float* dec_a2_in_b;
    const float* dec_a2_out_w;const float* dec_a2_out_b;
    const float* dec_lin1_w;  const float* dec_lin1_b;
    const float* dec_lin2_w;  const float* dec_lin2_b;
    const float* dec_ln3_w;   const float* dec_ln3_b;
    float* out;
};

__device__ __forceinline__ float ex2f(float x) {
    float y; asm("ex2.approx.ftz.f32 %0, %1;" : "=f"(y) : "f"(x)); return y;
}
__device__ __forceinline__ float rcpf(float x) {
    float y; asm("rcp.approx.ftz.f32 %0, %1;" : "=f"(y) : "f"(x)); return y;
}

// ---- packed f32x2 ops (Blackwell) ----
__device__ __forceinline__ u64 fma2(u64 a, u64 b, u64 c) {
    u64 d; asm("fma.rn.f32x2 %0, %1, %2, %3;" : "=l"(d) : "l"(a), "l"(b), "l"(c)); return d;
}
__device__ __forceinline__ u64 mul2(u64 a, u64 b) {
    u64 d; asm("mul.rn.f32x2 %0, %1, %2;" : "=l"(d) : "l"(a), "l"(b)); return d;
}
__device__ __forceinline__ u64 add2(u64 a, u64 b) {
    u64 d; asm("add.rn.f32x2 %0, %1, %2;" : "=l"(d) : "l"(a), "l"(b)); return d;
}
__device__ __forceinline__ u64 pack2(float lo, float hi) {
    u64 d; asm("mov.b64 %0, {%1, %2};" : "=l"(d) : "f"(lo), "f"(hi)); return d;
}
__device__ __forceinline__ void unpack2(u64 d, float& a, float& b) {
    asm("mov.b64 {%0, %1}, %2;" : "=f"(a), "=f"(b) : "l"(d));
}
__device__ __forceinline__ float hadd2(u64 d) {
    float a, b; unpack2(d, a, b); return a + b;
}

// Key-pair attention step: lanes = 2 keys vs 1 broadcast query.
__device__ __forceinline__ void qstep(u64 q0p, u64 q1p, u64 q2p,
                                      u64 xp, u64 yp, u64 zp,
                                      u64& aX, u64& aY, u64& aZ, u64& aL) {
    u64 d = fma2(q2p, zp, fma2(q1p, yp, mul2(q0p, xp)));
    float s0, s1; unpack2(d, s0, s1);
    u64 pp = pack2(ex2f(s0), ex2f(s1));
    aX = fma2(pp, xp, aX);
    aY = fma2(pp, yp, aY);
    aZ = fma2(pp, zp, aZ);
    aL = add2(aL, pp);
}
__device__ __forceinline__ void hsum4(u64 aX, u64 aY, u64 aZ, u64 aL,
                                      float& x, float& y, float& z, float& l) {
    x = hadd2(aX); y = hadd2(aY); z = hadd2(aZ); l = hadd2(aL);
}

// Query-pair step: lanes = (queryA, queryB), key broadcast in both lanes.
__device__ __forceinline__ void qpair_step(u64 qp0, u64 qp1, u64 qp2,
                                           float kx, float ky, float kz,
                                           u64& aX, u64& aY, u64& aZ, u64& aL) {
    u64 kxp = pack2(kx, kx), kyp = pack2(ky, ky), kzp = pack2(kz, kz);
    u64 d = fma2(qp2, kzp, fma2(qp1, kyp, mul2(qp0, kxp)));
    float sA, sB; unpack2(d, sA, sB);
    u64 pp = pack2(ex2f(sA), ex2f(sB));
    aX = fma2(pp, kxp, aX);
    aY = fma2(pp, kyp, aY);
    aZ = fma2(pp, kzp, aZ);
    aL = add2(aL, pp);
}
// Masked: reference ADDS tril(ones) -> +log2(e) in exp2 domain, per lane.
__device__ __forceinline__ void qpair_step_m(u64 qp0, u64 qp1, u64 qp2,
                                             float kx, float ky, float kz,
                                             int j, int rowA, int rowB,
                                             u64& aX, u64& aY, u64& aZ, u64& aL) {
    u64 kxp = pack2(kx, kx), kyp = pack2(ky, ky), kzp = pack2(kz, kz);
    u64 d = fma2(qp2, kzp, fma2(qp1, kyp, mul2(qp0, kxp)));
    float sA, sB; unpack2(d, sA, sB);
    sA += (j <= rowA) ? L2E : 0.f;
    sB += (j <= rowB) ? L2E : 0.f;
    u64 pp = pack2(ex2f(sA), ex2f(sB));
    aX = fma2(pp, kxp, aX);
    aY = fma2(pp, kyp, aY);
    aZ = fma2(pp, kzp, aZ);
    aL = add2(aL, pp);
}

// Fused two-value block reduction (2 barriers).
__device__ __forceinline__ void block_sum2(float& a, float& b, float* red) {
    #pragma unroll
    for (int o = 16; o; o >>= 1) {
        a += __shfl_xor_sync(0xffffffffu, a, o);
        b += __shfl_xor_sync(0xffffffffu, b, o);
    }
    int w = threadIdx.x >> 5;
    if ((threadIdx.x & 31) == 0) { red[w] = a; red[8 + w] = b; }
    __syncthreads();
    if (threadIdx.x < 16) {
        float x = red[threadIdx.x];
        x += __shfl_xor_sync(0x0000ffffu, x, 4);
        x += __shfl_xor_sync(0x0000ffffu, x, 2);
        x += __shfl_xor_sync(0x0000ffffu, x, 1);
        if ((threadIdx.x & 7) == 0) red[16 + (threadIdx.x >> 3)] = x;
    }
    __syncthreads();
    a = red[16]; b = red[17];
}

__device__ __forceinline__ void proj3(const float* w, const float* bias,
                                      float x0, float x1, float x2,
                                      float& o0, float& o1, float& o2) {
    o0 = fmaf(w[0], x0, fmaf(w[1], x1, fmaf(w[2], x2, bias[0])));
    o1 = fmaf(w[3], x0, fmaf(w[4], x1, fmaf(w[5], x2, bias[1])));
    o2 = fmaf(w[6], x0, fmaf(w[7], x1, fmaf(w[8], x2, bias[2])));
}
__device__ __forceinline__ void proj3T(const float* w,
                                       float x0, float x1, float x2,
                                       float& o0, float& o1, float& o2) {
    o0 = fmaf(w[0], x0, fmaf(w[3], x1, w[6] * x2));
    o1 = fmaf(w[1], x0, fmaf(w[4], x1, w[7] * x2));
    o2 = fmaf(w[2], x0, fmaf(w[5], x1, w[8] * x2));
}
// q' = (Wk^T (Wq x + bq)) * C_SCALE; bk dropped (cancels in softmax)
__device__ __forceinline__ void make_q(const float* in_w, const float* in_b,
                                       float x0, float x1, float x2,
                                       float& q0, float& q1, float& q2) {
    float t0, t1, t2;
    proj3(in_w, in_b, x0, x1, x2, t0, t1, t2);
    proj3T(in_w + 9, t0, t1, t2, q0, q1, q2);
    q0 *= C_SCALE; q1 *= C_SCALE; q2 *= C_SCALE;
}

// Weight staging WITHOUT trailing sync — caller's next barrier covers visibility.
__device__ __forceinline__ void load_wff_nosync(float4* s_wff, const float* w1,
                                                const float* b1, const float* w2) {
    for (int h = threadIdx.x; h < HIDN; h += 256) {
        s_wff[2*h]   = make_float4(w1[h*3], w1[h*3+1], w1[h*3+2], b1[h]);
        s_wff[2*h+1] = make_float4(w2[h], w2[HIDN + h], w2[2*HIDN + h], 0.f);
    }
}

// pos_enc row s: first 3 sin columns, invf[e] = 10000^(-2e/256)
__device__ __forceinline__ void pos3(int s, float& p0, float& p1, float& p2) {
    const float f1 = (float)0.93057204868496882;  // 10000^(-2/256)
    const float f2 = (float)0.86596432336006538;  // 10000^(-4/256)
    float a0 = (float)s;
    p0 = sinf(a0);
    p1 = sinf(a0 * f1);
    p2 = sinf(a0 * f2);
}

// One CTA = one batch. Grid caps occupancy at ~7 CTAs/SM.
__global__ void __launch_bounds__(256, 7)
fused_transformer_kernel(Params P) {
    // 16KB union s_U (float view sf[0..4096)), time-multiplexed:
    //   attn: enc keys SoA [0..768) | pT SoA [768..1152) | partials f4[288..800)
    //         | q SoA [3200..3584)
    //   ffn:  packed AoS weights (2 float4 per h) over s_U[0..1024)
    __shared__ __align__(16) float4 s_U[1024];
    __shared__ float s_x2[SIN * 3];
    __shared__ float s_R[SIN * 3];
    __shared__ float s_E[SIN * 3];
    __shared__ float s_red[18];

    float* const sf = (float*)s_U;
    float* const sX = sf;            // 256 floats (enc keys / enc_out keys)
    float* const sY = sf + 256;
    float* const sZ = sf + 512;
    float* const pX = sf + 768;      // 128 floats (pT keys)
    float* const pY = sf + 896;
    float* const pZ = sf + 1024;
    float4* const s_part = s_U + 288;  // attn partials
    float* const qQX = sf + 3200;    // 128 floats: precomputed decoder queries
    float* const qQY = sf + 3328;
    float* const qQZ = sf + 3456;

    const int b    = blockIdx.x;
    const int t    = threadIdx.x;
    const int r128 = t & 127, half2 = t >> 7;
    const int r64  = t & 63,  q4    = t >> 6;
    const float INV768 = 1.0f / 768.0f;
    const float INV384 = 1.0f / 384.0f;

    float pe0, pe1, pe2;
    pos3(t, pe0, pe1, pe2);

    // ================= ENCODER =================
    // E1: pX = X + pos_enc -> SoA keys
    {
        const float* xr = P.X + ((size_t)b * SIN + t) * 3;
        sX[t] = xr[0] + pe0;
        sY[t] = xr[1] + pe1;
        sZ[t] = xr[2] + pe2;
    }
    __syncthreads();

    // E2 + LN1 fused: attention -> residual r stays in regs -> LN reduction.
    // Enc FFN weights staged inside the LN (after block_sum2, keys provably dead).
    {
        float x0 = sX[t], x1 = sY[t], x2v = sZ[t];
        float q0, q1, q2;
        make_q(P.enc_in_w, P.enc_in_b, x0, x1, x2v, q0, q1, q2);
        u64 q0p = pack2(q0, q0), q1p = pack2(q1, q1), q2p = pack2(q2, q2);
        u64 aX = 0, aY = 0, aZ = 0, aL = 0;
        const double2* X2 = (const double2*)sX;
        const double2* Y2 = (const double2*)sY;
        const double2* Z2 = (const double2*)sZ;
        #pragma unroll 4
        for (int i = 0; i < 64; ++i) {
            double2 dx = X2[i], dy = Y2[i], dz = Z2[i];
            qstep(q0p, q1p, q2p,
                  __double_as_longlong(dx.x), __double_as_longlong(dy.x), __double_as_longlong(dz.x),
                  aX, aY, aZ, aL);
            qstep(q0p, q1p, q2p,
                  __double_as_longlong(dx.y), __double_as_longlong(dy.y), __double_as_longlong(dz.y),
                  aX, aY, aZ, aL);
        }
        float ax, ay, az, l;
        hsum4(aX, aY, aZ, aL, ax, ay, az, l);
        float inv = rcpf(l);
        float v0, v1, v2;
        proj3(P.enc_in_w + 18, P.enc_in_b + 6, ax*inv, ay*inv, az*inv, v0, v1, v2);
        float r0, r1, r2;
        proj3(P.enc_out_w, P.enc_out_b, v0, v1, v2, r0, r1, r2);
        r0 += x0; r1 += x1; r2 += x2v;

        // LN1 over 768 elems — r in registers.
        float s1 = r0 + r1 + r2;
        float s2 = fmaf(r0, r0, fmaf(r1, r1, r2 * r2));
        block_sum2(s1, s2, s_red);
        // All E2 key reads complete (barrier above) -> stage FFN weights over keys.
        load_wff_nosync(s_U, P.enc_lin1_w, P.enc_lin1_b, P.enc_lin2_w);
        float mean = s1 * INV768;
        float var  = fmaf(-mean, mean, s2 * INV768);
        float rs = rsqrtf(var + 1e-5f);
        s_x2[t*3+0] = (r0 - mean) * rs * P.enc_ln1_w[t*3+0] + P.enc_ln1_b[t*3+0];
        s_x2[t*3+1] = (r1 - mean) * rs * P.enc_ln1_w[t*3+1] + P.enc_ln1_b[t*3+1];
        s_x2[t*3+2] = (r2 - mean) * rs * P.enc_ln1_w[t*3+2] + P.enc_ln1_b[t*3+2];
    }
    __syncthreads();   // covers s_x2 writes AND weight staging

    // E3: FFN. 2 rows {r128, r128+128} x 256 hidden (half2 split).
    {
        int rowA = r128, rowB = r128 + 128;
        float xA0=s_x2[rowA*3], xA1=s_x2[rowA*3+1], xA2=s_x2[rowA*3+2];
        float xB0=s_x2[rowB*3], xB1=s_x2[rowB*3+1], xB2=s_x2[rowB*3+2];
        float aA0=0.f,aA1=0.f,aA2=0.f, aB0=0.f,aB1=0.f,aB2=0.f;
        int h0 = half2 * 256;
        #pragma unroll 4
        for (int h = h0; h < h0 + 256; ++h) {
            float4 w1 = s_U[2*h];
            float4 w2 = s_U[2*h+1];
            float tA = fmaxf(fmaf(w1.x, xA0, fmaf(w1.y, xA1, fmaf(w1.z, xA2, w1.w))), 0.f);
            float tB = fmaxf(fmaf(w1.x, xB0, fmaf(w1.y, xB1, fmaf(w1.z, xB2, w1.w))), 0.f);
            aA0 = fmaf(tA, w2.x, aA0); aA1 = fmaf(tA, w2.y, aA1); aA2 = fmaf(tA, w2.z, aA2);
            aB0 = fmaf(tB, w2.x, aB0); aB1 = fmaf(tB, w2.y, aB1); aB2 = fmaf(tB, w2.z, aB2);
        }
        float* dst = half2 ? s_R : s_E;
        dst[rowA*3+0]=aA0; dst[rowA*3+1]=aA1; dst[rowA*3+2]=aA2;
        dst[rowB*3+0]=aB0; dst[rowB*3+1]=aB1; dst[rowB*3+2]=aB2;
    }
    __syncthreads();   // FFN partials visible; weights + keys region dead

    // combine + LN2 fused -> enc_out keys (SoA) ; also pT load + q_self precompute.
    {
        float r0 = s_E[t*3+0] + s_R[t*3+0] + P.enc_lin2_b[0] + s_x2[t*3+0];
        float r1 = s_E[t*3+1] + s_R[t*3+1] + P.enc_lin2_b[1] + s_x2[t*3+1];
        float r2 = s_E[t*3+2] + s_R[t*3+2] + P.enc_lin2_b[2] + s_x2[t*3+2];
        float s1 = r0 + r1 + r2;
        float s2 = fmaf(r0, r0, fmaf(r1, r1, r2 * r2));
        block_sum2(s1, s2, s_red);
        float mean = s1 * INV768;
        float var  = fmaf(-mean, mean, s2 * INV768);
        float rs = rsqrtf(var + 1e-5f);
        sX[t] = (r0 - mean) * rs * P.enc_ln2_w[t*3+0] + P.enc_ln2_b[t*3+0];
        sY[t] = (r1 - mean) * rs * P.enc_ln2_w[t*3+1] + P.enc_ln2_b[t*3+1];
        sZ[t] = (r2 - mean) * rs * P.enc_ln2_w[t*3+2] + P.enc_ln2_b[t*3+2];
        if (t < SPR) {
            const float* tr = P.T + ((size_t)b * SPR + t) * 3;
            float x0 = tr[0] + pe0, x1 = tr[1] + pe1, x2v = tr[2] + pe2;
            pX[t] = x0; pY[t] = x1; pZ[t] = x2v;
            float q0, q1, q2;
            make_q(P.dec_a1_in_w, P.dec_a1_in_b, x0, x1, x2v, q0, q1, q2);
            qQX[t] = q0; qQY[t] = q1; qQZ[t] = q2;
        }
    }
    __syncthreads();

    // ================= DECODER =================
    // D2: dec self-attn. Query-pair {r64, r64+64} (q from smem) x 32-key quarter.
    {
        int rowA = r64, rowB = r64 + 64;
        u64 qp0 = pack2(qQX[rowA], qQX[rowB]);
        u64 qp1 = pack2(qQY[rowA], qQY[rowB]);
        u64 qp2 = pack2(qQZ[rowA], qQZ[rowB]);
        u64 aX = 0, aY = 0, aZ = 0, aL = 0;
        int j0 = q4 * 32;
        #pragma unroll 4
        for (int j = j0; j < j0 + 32; ++j)
            qpair_step_m(qp0, qp1, qp2, pX[j], pY[j], pZ[j], j, rowA, rowB, aX, aY, aZ, aL);
        float lA,lB, axA,axB, ayA,ayB, azA,azB;
        unpack2(aL, lA, lB); unpack2(aX, axA, axB);
        unpack2(aY, ayA, ayB); unpack2(aZ, azA, azB);
        s_part[rowA*4 + q4] = make_float4(lA, axA, ayA, azA);
        s_part[rowB*4 + q4] = make_float4(lB, axB, ayB, azB);
    }
    __syncthreads();
    // D2 merge + LN fused -> s_x2 ; cross-query precompute into qQ.
    {
        float r0 = 0.f, r1 = 0.f, r2 = 0.f;
        if (t < SPR) {
            float4 p0 = s_part[t*4], p1 = s_part[t*4+1], p2 = s_part[t*4+2], p3 = s_part[t*4+3];
            float inv = rcpf(p0.x + p1.x + p2.x + p3.x);
            float v0, v1, v2;
            proj3(P.dec_a1_in_w + 18, P.dec_a1_in_b + 6,
                  (p0.y+p1.y+p2.y+p3.y)*inv, (p0.z+p1.z+p2.z+p3.z)*inv, (p0.w+p1.w+p2.w+p3.w)*inv,
                  v0, v1, v2);
            proj3(P.dec_a1_out_w, P.dec_a1_out_b, v0, v1, v2, r0, r1, r2);
            r0 += pX[t]; r1 += pY[t]; r2 += pZ[t];
        }
        float s1 = r0 + r1 + r2;
        float s2 = fmaf(r0, r0, fmaf(r1, r1, r2 * r2));
        block_sum2(s1, s2, s_red);
        if (t < SPR) {
            float mean = s1 * INV384;
            float var  = fmaf(-mean, mean, s2 * INV384);
            float rs = rsqrtf(var + 1e-5f);
            float o0 = (r0 - mean) * rs * P.dec_ln1_w[t*3+0] + P.dec_ln1_b[t*3+0];
            float o1 = (r1 - mean) * rs * P.dec_ln1_w[t*3+1] + P.dec_ln1_b[t*3+1];
            float o2 = (r2 - mean) * rs * P.dec_ln1_w[t*3+2] + P.dec_ln1_b[t*3+2];
            s_x2[t*3+0] = o0; s_x2[t*3+1] = o1; s_x2[t*3+2] = o2;
            float q0, q1, q2;
            make_q(P.dec_a2_in_w, P.dec_a2_in_b, o0, o1, o2, q0, q1, q2);
            qQX[t] = q0; qQY[t] = q1; qQZ[t] = q2;
        }
    }
    __syncthreads();

    // D4: cross-attn. Query-pair {r64, r64+64} (q from smem) x 64-key quarter.
    {
        int rowA = r64, rowB = r64 + 64;
        u64 qp0 = pack2(qQX[rowA], qQX[rowB]);
        u64 qp1 = pack2(qQY[rowA], qQY[rowB]);
        u64 qp2 = pack2(qQZ[rowA], qQZ[rowB]);
        u64 aX = 0, aY = 0, aZ = 0, aL = 0;
        int j0 = q4 * 64;
        #pragma unroll 4
        for (int j = j0; j < j0 + 64; ++j)
            qpair_step(qp0, qp1, qp2, sX[j], sY[j], sZ[j], aX, aY, aZ, aL);
        float lA,lB, axA,axB, ayA,ayB, azA,azB;
        unpack2(aL, lA, lB); unpack2(aX, axA, axB);
        unpack2(aY, ayA, ayB); unpack2(aZ, azA, azB);
        s_part[rowA*4 + q4] = make_float4(lA, axA, ayA, azA);
        s_part[rowB*4 + q4] = make_float4(lB, axB, ayB, azB);
    }
    __syncthreads();
    // D4 merge + LN fused -> x3 in s_x2. Dec FFN weights staged after block_sum2
    // (all s_U reads — partials/keys/queries — provably complete there).
    {
        float r0 = 0.f, r1 = 0.f, r2 = 0.f;
        if (t < SPR) {
            float4 p0 = s_part[t*4], p1 = s_part[t*4+1], p2 = s_part[t*4+2], p3 = s_part[t*4+3];
            float inv = rcpf(p0.x + p1.x + p2.x + p3.x);
            float v0, v1, v2;
            proj3(P.dec_a2_in_w + 18, P.dec_a2_in_b + 6,
                  (p0.y+p1.y+p2.y+p3.y)*inv, (p0.z+p1.z+p2.z+p3.z)*inv, (p0.w+p1.w+p2.w+p3.w)*inv,
                  v0, v1, v2);
            proj3(P.dec_a2_out_w, P.dec_a2_out_b, v0, v1, v2, r0, r1, r2);
            r0 += s_x2[t*3+0]; r1 += s_x2[t*3+1]; r2 += s_x2[t*3+2];
        }
        float s1 = r0 + r1 + r2;
        float s2 = fmaf(r0, r0, fmaf(r1, r1, r2 * r2));
        block_sum2(s1, s2, s_red);
        load_wff_nosync(s_U, P.dec_lin1_w, P.dec_lin1_b, P.dec_lin2_w);
        if (t < SPR) {
            float mean = s1 * INV384;
            float var  = fmaf(-mean, mean, s2 * INV384);
            float rs = rsqrtf(var + 1e-5f);
            s_x2[t*3+0] = (r0 - mean) * rs * P.dec_ln1_w[t*3+0] + P.dec_ln1_b[t*3+0];
            s_x2[t*3+1] = (r1 - mean) * rs * P.dec_ln1_w[t*3+1] + P.dec_ln1_b[t*3+1];
            s_x2[t*3+2] = (r2 - mean) * rs * P.dec_ln1_w[t*3+2] + P.dec_ln1_b[t*3+2];
        }
    }
    __syncthreads();   // covers x3 writes AND weight staging

    // D5: dec FFN. 2 rows {r64, r64+64} x 128 hidden (quarter q4).
    {
        int rowA = r64, rowB = r64 + 64;
        float xA0=s_x2[rowA*3], xA1=s_x2[rowA*3+1], xA2=s_x2[rowA*3+2];
        float xB0=s_x2[rowB*3], xB1=s_x2[rowB*3+1], xB2=s_x2[rowB*3+2];
        float aA0=0.f,aA1=0.f,aA2=0.f, aB0=0.f,aB1=0.f,aB2=0.f;
        int h0 = q4 * 128;
        #pragma unroll 4
        for (int h = h0; h < h0 + 128; ++h) {
            float4 w1 = s_U[2*h];
            float4 w2 = s_U[2*h+1];
            float tA = fmaxf(fmaf(w1.x, xA0, fmaf(w1.y, xA1, fmaf(w1.z, xA2, w1.w))), 0.f);
            float tB = fmaxf(fmaf(w1.x, xB0, fmaf(w1.y, xB1, fmaf(w1.z, xB2, w1.w))), 0.f);
            aA0 = fmaf(tA, w2.x, aA0); aA1 = fmaf(tA, w2.y, aA1); aA2 = fmaf(tA, w2.z, aA2);
            aB0 = fmaf(tB, w2.x, aB0); aB1 = fmaf(tB, w2.y, aB1); aB2 = fmaf(tB, w2.z, aB2);
        }
        float* dst = (q4 < 2) ? s_R : s_E;
        int off = (q4 & 1) * 384;
        dst[off + rowA*3+0]=aA0; dst[off + rowA*3+1]=aA1; dst[off + rowA*3+2]=aA2;
        dst[off + rowB*3+0]=aB0; dst[off + rowB*3+1]=aB1; dst[off + rowB*3+2]=aB2;
    }
    __syncthreads();

    // final combine + LN3 fused -> global output (no trailing barrier).
    {
        float r0 = 0.f, r1 = 0.f, r2 = 0.f;
        if (t < SPR) {
            r0 = s_R[t*3+0] + s_R[384+t*3+0] + s_E[t*3+0] + s_E[384+t*3+0]
               + P.dec_lin2_b[0] + s_x2[t*3+0];
            r1 = s_R[t*3+1] + s_R[384+t*3+1] + s_E[t*3+1] + s_E[384+t*3+1]
               + P.dec_lin2_b[1] + s_x2[t*3+1];
            r2 = s_R[t*3+2] + s_R[384+t*3+2] + s_E[t*3+2] + s_E[384+t*3+2]
               + P.dec_lin2_b[2] + s_x2[t*3+2];
        }
        float s1 = r0 + r1 + r2;
        float s2 = fmaf(r0, r0, fmaf(r1, r1, r2 * r2));
        block_sum2(s1, s2, s_red);
        if (t < SPR) {
            float mean = s1 * INV384;
            float var  = fmaf(-mean, mean, s2 * INV384);
            float rs = rsqrtf(var + 1e-5f);
            float* o = P.out + ((size_t)b * SPR + t) * 3;
            o[0] = (r0 - mean) * rs * P.dec_ln3_w[t*3+0] + P.dec_ln3_b[t*3+0];
            o[1] = (r1 - mean) * rs * P.dec_ln3_w[t*3+1] + P.dec_ln3_b[t*3+1];
            o[2] = (r2 - mean) * rs * P.dec_ln3_w[t*3+2] + P.dec_ln3_b[t*3+2];
        }
    }
}

extern "C" void kernel_launch(void* const* d_in, const int* in_sizes, int n_in,
                              void* d_out, int out_size) {
    (void)in_sizes; (void)n_in; (void)out_size;
    Params P;
    P.X            = (const float*)d_in[0];
    P.T            = (const float*)d_in[1];
    P.enc_in_w     = (const float*)d_in[2];
    P.enc_in_b     = (const float*)d_in[3];
    P.enc_out_w    = (const float*)d_in[4];
    P.enc_out_b    = (const float*)d_in[5];
    P.enc_ln1_w    = (const float*)d_in[6];
    P.enc_ln1_b    = (const float*)d_in[7];
    P.enc_lin1_w   = (const float*)d_in[8];
    P.enc_lin1_b   = (const float*)d_in[9];
    P.enc_lin2_w   = (const float*)d_in[10];
    P.enc_lin2_b   = (const float*)d_in[11];
    P.enc_ln2_w    = (const float*)d_in[12];
    P.enc_ln2_b    = (const float*)d_in[13];
    P.dec_a1_in_w  = (const float*)d_in[14];
    P.dec_a1_in_b  = (const float*)d_in[15];
    P.dec_a1_out_w = (const float*)d_in[16];
    P.dec_a1_out_b = (const float*)d_in[17];
    P.dec_ln1_w    = (const float*)d_in[18];
    P.dec_ln1_b    = (const float*)d_in[19];
    P.dec_a2_in_w  = (const float*)d_in[20];
    P.dec_a2_in_b  = (const float*)d_in[21];
    P.dec_a2_out_w = (const float*)d_in[22];
    P.dec_a2_out_b = (const float*)d_in[23];
    P.dec_lin1_w   = (const float*)d_in[24];
    P.dec_lin1_b   = (const float*)d_in[25];
    P.dec_lin2_w   = (const float*)d_in[26];
    P.dec_lin2_b   = (const float*)d_in[27];
    P.dec_ln3_w    = (const float*)d_in[28];
    P.dec_ln3_b    = (const float*)d_in[29];
    P.out          = (float*)d_out;

    fused_transformer_kernel<<<NB, 256>>>(P);
}